// round 8
// baseline (speedup 1.0000x reference)
#include <cuda_runtime.h>
#include <cuda_fp16.h>
#include <math_constants.h>
#include <cstdint>

// Problem constants
#define DD     1024
#define NB     64
#define SS     36
#define LL     32
#define SMOOTHF 9.0f
#define LAMBDAF 6.0f
#define EPSF   1e-8f

#define MROWS  (NB*SS)       // 2304 image rows
#define CROWS  (NB*LL)       // 2048 caption rows
#define AROWS  (2*MROWS)     // 4608 = [images ; Y]
#define KSPLIT 2048          // K after fp16 [hi|lo] (A-side) / [hi|hi] (B-side) concat
#define XCOLS  CROWS         // 2048

#define BK 64                        // fp16 elems per chunk = 128 B rows
#define NCHUNK (KSPLIT / BK)         // 32
#define NSTAGE 3

// Scratch (static device globals; allocation forbidden)
__device__ __half g_A2[(size_t)AROWS * KSPLIT];  // [images-split ; Y-split]
__device__ __half g_B2[(size_t)CROWS * KSPLIT];  // captions split
__device__ __half g_BW[(size_t)DD   * KSPLIT];   // W_g^T split
__device__ float g_X[(size_t)AROWS * XCOLS];     // fused GEMM output fp32
__device__ float g_G[NB * SS * SS];
__device__ float g_w1[CROWS];

// ---------------------------------------------------------------------------
// PTX helpers (base-ISA only: cp.async, ldmatrix, mma.sync)
// ---------------------------------------------------------------------------
__device__ __forceinline__ uint32_t smem_u32(const void* p) {
    uint32_t a;
    asm("{ .reg .u64 t; cvta.to.shared.u64 t, %1; cvt.u32.u64 %0, t; }" : "=r"(a) : "l"(p));
    return a;
}
#define CP_ASYNC16(dst, src) \
    asm volatile("cp.async.cg.shared.global [%0], [%1], 16;\n" :: "r"(dst), "l"(src))
#define CP_COMMIT() asm volatile("cp.async.commit_group;\n" ::: "memory")
#define CP_WAIT(n)  asm volatile("cp.async.wait_group %0;\n" :: "n"(n) : "memory")

__device__ __forceinline__ void ldsm4(uint32_t* r, uint32_t addr) {
    asm volatile("ldmatrix.sync.aligned.m8n8.x4.shared.b16 {%0,%1,%2,%3}, [%4];"
                 : "=r"(r[0]), "=r"(r[1]), "=r"(r[2]), "=r"(r[3]) : "r"(addr));
}
__device__ __forceinline__ void mma16816(float* c, const uint32_t* a,
                                         uint32_t b0, uint32_t b1) {
    asm volatile("mma.sync.aligned.m16n8k16.row.col.f32.f16.f16.f32 "
                 "{%0,%1,%2,%3}, {%4,%5,%6,%7}, {%8,%9}, {%0,%1,%2,%3};"
                 : "+f"(c[0]), "+f"(c[1]), "+f"(c[2]), "+f"(c[3])
                 : "r"(a[0]), "r"(a[1]), "r"(a[2]), "r"(a[3]), "r"(b0), "r"(b1));
}
// SW128 swizzle for 128B rows
__device__ __forceinline__ uint32_t swz(int row, int seg) {
    return (uint32_t)(row * 128 + (seg ^ ((row & 7) << 4)));
}

// ---------------------------------------------------------------------------
// Split kernels (fp16 two-term)
// A-side pattern: [hi | lo]; B-side pattern: [hi | hi]
// ---------------------------------------------------------------------------
__global__ void split_rows_kernel(const float* __restrict__ src, __half* __restrict__ dst,
                                  int second_is_lo)
{
    int idx = blockIdx.x * 256 + threadIdx.x;
    int row = idx >> 10, col = idx & 1023;
    float f = src[idx];
    __half hi = __float2half(f);
    __half sec = second_is_lo ? __float2half(f - __half2float(hi)) : hi;
    size_t r = (size_t)row * KSPLIT;
    dst[r + col] = hi;
    dst[r + 1024 + col] = sec;
}

// W_g transpose + split (B-side [hi|hi]): g_BW[n][k] = W_g[k][n]
__global__ void split_w_kernel(const float* __restrict__ W)
{
    __shared__ float t[32][33];
    int k0 = blockIdx.y * 32, n0 = blockIdx.x * 32;
    int tx = threadIdx.x, ty = threadIdx.y;
    t[ty][tx] = W[(size_t)(k0 + ty) * DD + n0 + tx];
    __syncthreads();
    float f = t[tx][ty];                       // = W[k0+tx][n0+ty]
    __half hi = __float2half(f);
    size_t r = (size_t)(n0 + ty) * KSPLIT;
    g_BW[r + k0 + tx] = hi;
    g_BW[r + 1024 + k0 + tx] = hi;
}

// ---------------------------------------------------------------------------
// HMMA NT GEMM: C[m,n] = sum_k A[m,k]*B[n,k], K = KSPLIT.
// 64x64 warp tiles (MT=4, NT2=4), single-buffered fragments, 3-stage cp.async.
// mode 0: write fp32 C (ldc). mode 1: write split fp16 rows [hi|lo] into Aout.
// ---------------------------------------------------------------------------
template<int BM, int BN, int WARPS_M, int WARPS_N, int MIN_CTAS>
__global__ __launch_bounds__(WARPS_M * WARPS_N * 32, MIN_CTAS)
void gemm_mma_kernel(const __half* __restrict__ A,
                     const __half* __restrict__ B,
                     float* __restrict__ C,
                     __half* __restrict__ Aout,
                     int mode, int ldc)
{
    constexpr int THREADS = WARPS_M * WARPS_N * 32;
    constexpr int MT  = BM / WARPS_M / 16;   // 4: A 16-row subtiles per warp
    constexpr int NT2 = BN / WARPS_N / 16;   // 4: B 16-row ldsm tiles per warp
    constexpr int NJ  = NT2 * 2;             // 8: n8 column groups per warp
    constexpr int A_BYTES = BM * 128;
    constexpr int B_BYTES = BN * 128;
    constexpr int STAGE_BYTES = A_BYTES + B_BYTES;
    constexpr int A_IT = BM * 8 / THREADS;
    constexpr int B_IT = BN * 8 / THREADS;

    extern __shared__ char smem_raw[];
    const uint32_t sbase = (smem_u32(smem_raw) + 1023u) & ~1023u;

    const int tid = threadIdx.x;
    const int wid = tid >> 5, lane = tid & 31;
    const int wm = wid / WARPS_N;
    const int wn = wid % WARPS_N;
    const size_t arow0 = (size_t)blockIdx.y * BM;
    const size_t brow0 = (size_t)blockIdx.x * BN;

    const int lr = lane & 15;
    const int lseg = (lane >> 4) * 16;

    float acc[MT][NJ][4];
#pragma unroll
    for (int mt = 0; mt < MT; mt++)
#pragma unroll
        for (int j = 0; j < NJ; j++)
#pragma unroll
            for (int e = 0; e < 4; e++) acc[mt][j][e] = 0.f;

    uint32_t af[MT][4], bf[NT2][4];

    const char* Abase = (const char*)(A + arow0 * KSPLIT);
    const char* Bbase = (const char*)(B + brow0 * KSPLIT);
    auto load_chunk = [&](int c, int s) {
        const uint32_t sA = sbase + s * STAGE_BYTES;
        const uint32_t sB = sA + A_BYTES;
        const size_t cb = (size_t)c * 128;
#pragma unroll
        for (int i = 0; i < A_IT; i++) {
            int p = tid + i * THREADS;
            int r = p >> 3, seg = (p & 7) * 16;
            CP_ASYNC16(sA + swz(r, seg), Abase + (size_t)r * (KSPLIT * 2) + cb + seg);
        }
#pragma unroll
        for (int i = 0; i < B_IT; i++) {
            int p = tid + i * THREADS;
            int r = p >> 3, seg = (p & 7) * 16;
            CP_ASYNC16(sB + swz(r, seg), Bbase + (size_t)r * (KSPLIT * 2) + cb + seg);
        }
        CP_COMMIT();
    };

    load_chunk(0, 0);
    load_chunk(1, 1);

    for (int c = 0; c < NCHUNK; c++) {
        // Ensure chunk c complete (committed >=2 iterations ago).
        if (c + 1 < NCHUNK) { CP_WAIT(1); } else { CP_WAIT(0); }
        __syncthreads();   // visibility of chunk c; all warps done with stage (c+2)%3's old tenant
        if (c + 2 < NCHUNK) load_chunk(c + 2, (c + 2) % NSTAGE);
        const int s = c % NSTAGE;
        const uint32_t sA = sbase + s * STAGE_BYTES;
        const uint32_t sB = sA + A_BYTES;
#pragma unroll
        for (int kk = 0; kk < 4; kk++) {
#pragma unroll
            for (int mt = 0; mt < MT; mt++)
                ldsm4(af[mt], sA + swz(wm * (MT * 16) + mt * 16 + lr, kk * 32 + lseg));
#pragma unroll
            for (int nt = 0; nt < NT2; nt++)
                ldsm4(bf[nt], sB + swz(wn * (NT2 * 16) + nt * 16 + lr, kk * 32 + lseg));
#pragma unroll
            for (int mt = 0; mt < MT; mt++)
#pragma unroll
                for (int nt = 0; nt < NT2; nt++)
#pragma unroll
                    for (int h = 0; h < 2; h++)
                        mma16816(acc[mt][nt * 2 + h], af[mt], bf[nt][h], bf[nt][h + 2]);
        }
    }

    // Epilogue. C-frag mapping: lane l -> rows (l>>2, l>>2+8), cols 2*(l&3)+{0,1}.
    const int r0 = lane >> 2;
    const int cb2 = 2 * (lane & 3);
    if (mode == 0) {
#pragma unroll
        for (int mt = 0; mt < MT; mt++) {
#pragma unroll
            for (int j = 0; j < NJ; j++) {
                size_t row = arow0 + wm * (MT * 16) + mt * 16 + r0;
                size_t col = brow0 + wn * (NJ * 8) + j * 8 + cb2;
                *(float2*)(C + row * ldc + col)       = make_float2(acc[mt][j][0], acc[mt][j][1]);
                *(float2*)(C + (row + 8) * ldc + col) = make_float2(acc[mt][j][2], acc[mt][j][3]);
            }
        }
    } else {
#pragma unroll
        for (int mt = 0; mt < MT; mt++) {
#pragma unroll
            for (int j = 0; j < NJ; j++) {
                int col = (int)brow0 + wn * (NJ * 8) + j * 8 + cb2;   // < 1024
#pragma unroll
                for (int h = 0; h < 2; h++) {
                    size_t row = arow0 + wm * (MT * 16) + mt * 16 + r0 + h * 8;
                    __half* dr = Aout + row * KSPLIT;
                    float f0 = acc[mt][j][2 * h], f1 = acc[mt][j][2 * h + 1];
                    __half h0 = __float2half(f0);
                    __half h1 = __float2half(f1);
                    __half l0 = __float2half(f0 - __half2float(h0));
                    __half l1 = __float2half(f1 - __half2float(h1));
                    __half2 hv; hv.x = h0; hv.y = h1;
                    __half2 lv; lv.x = l0; lv.y = l1;
                    *(__half2*)(dr + col)        = hv;   // [hi | lo]
                    *(__half2*)(dr + 1024 + col) = lv;
                }
            }
        }
    }
}

// ---------------------------------------------------------------------------
// Per-image Gram matrix
// ---------------------------------------------------------------------------
__global__ void gram_kernel(const float* __restrict__ images)
{
    __shared__ float T[SS][65];
    const int b = blockIdx.x;
    const int tid = threadIdx.x;
    float acc[6] = {0.f, 0.f, 0.f, 0.f, 0.f, 0.f};
    for (int d0 = 0; d0 < DD; d0 += 64) {
        __syncthreads();
        for (int i = tid; i < SS * 64; i += 256) {
            int r = i / 64, c = i % 64;
            T[r][c] = images[((size_t)b * SS + r) * DD + d0 + c];
        }
        __syncthreads();
#pragma unroll
        for (int pi = 0; pi < 6; pi++) {
            int p = tid + pi * 256;
            if (p < SS * SS) {
                int s = p / SS, s2 = p % SS;
                float sum = 0.f;
#pragma unroll
                for (int k = 0; k < 64; k++) sum += T[s][k] * T[s2][k];
                acc[pi] += sum;
            }
        }
    }
#pragma unroll
    for (int pi = 0; pi < 6; pi++) {
        int p = tid + pi * 256;
        if (p < SS * SS) g_G[b * SS * SS + p] = acc[pi];
    }
}

__global__ void w1_kernel(const float* __restrict__ captions)
{
    const int row = blockIdx.x * 8 + (threadIdx.x >> 5);
    const int lane = threadIdx.x & 31;
    const float* p = captions + (size_t)row * DD;
    float s = 0.f;
    for (int k = lane; k < DD; k += 32) { float v = p[k]; s += v * v; }
#pragma unroll
    for (int o = 16; o; o >>= 1) s += __shfl_xor_sync(0xffffffffu, s, o);
    if (lane == 0) g_w1[row] = sqrtf(s);
}

// ---------------------------------------------------------------------------
// Final epilogue: one block per (caption i, image b)
// ---------------------------------------------------------------------------
__global__ __launch_bounds__(128)
void epilogue_kernel(const int* __restrict__ cap_lens, float* __restrict__ out)
{
    const int i = blockIdx.x;
    const int b = blockIdx.y;

    __shared__ float sA[SS][LL];
    __shared__ float sC[SS][LL];
    __shared__ float sQ[SS][LL];
    __shared__ float sG[SS][SS];
    __shared__ float snorm[SS];

    const int tid = threadIdx.x;
    const int len = cap_lens[i];

    for (int p = tid; p < SS * SS; p += 128)
        sG[p / SS][p % SS] = g_G[b * SS * SS + p];

    for (int p = tid; p < SS * LL; p += 128) {
        int s = p / LL, l = p % LL;
        size_t col = (size_t)i * LL + l;
        float a = g_X[(size_t)(MROWS + b * SS + s) * XCOLS + col];  // attn logits (Y.cap)
        a = (a > 0.f) ? a : 0.1f * a;
        if (l >= len) a = 0.f;
        sA[s][l] = a;
        sC[s][l] = g_X[(size_t)(b * SS + s) * XCOLS + col];          // cap . img
    }
    __syncthreads();

    if (tid < SS) {
        float s2 = 0.f;
#pragma unroll
        for (int l = 0; l < LL; l++) { float v = sA[tid][l]; s2 += v * v; }
        snorm[tid] = 1.f / (sqrtf(s2) + EPSF);
    }
    __syncthreads();

    if (tid < LL) {
        const int l = tid;
        float vals[SS];
        float m = -CUDART_INF_F;
#pragma unroll
        for (int s = 0; s < SS; s++) {
            float v = sA[s][l] * snorm[s] * SMOOTHF;
            vals[s] = v;
            m = fmaxf(m, v);
        }
        float sum = 0.f;
#pragma unroll
        for (int s = 0; s < SS; s++) {
            float e = expf(vals[s] - m);
            vals[s] = e;
            sum += e;
        }
        float inv = 1.f / sum;
#pragma unroll
        for (int s = 0; s < SS; s++) sA[s][l] = vals[s] * inv;
    }
    __syncthreads();

    for (int p = tid; p < SS * LL; p += 128) {
        int s = p / LL, l = p % LL;
        float sum = 0.f;
#pragma unroll
        for (int s2 = 0; s2 < SS; s2++) sum += sG[s][s2] * sA[s2][l];
        sQ[s][l] = sum;
    }
    __syncthreads();

    if (tid < LL) {
        const int l = tid;
        float w12 = 0.f, w2q = 0.f;
#pragma unroll
        for (int s = 0; s < SS; s++) {
            float p = sA[s][l];
            w12 += p * sC[s][l];
            w2q += p * sQ[s][l];
        }
        float w2 = sqrtf(fmaxf(w2q, 0.f));
        float w1 = g_w1[i * LL + l];
        float r = w12 / fmaxf(w1 * w2, EPSF);

        float z = (l < len) ? r * LAMBDAF : -CUDART_INF_F;
        float m = z;
#pragma unroll
        for (int o = 16; o; o >>= 1) m = fmaxf(m, __shfl_xor_sync(0xffffffffu, m, o));
        float e = (l < len) ? expf(z - m) : 0.f;
#pragma unroll
        for (int o = 16; o; o >>= 1) e += __shfl_xor_sync(0xffffffffu, e, o);
        if (l == 0) out[b * NB + i] = (logf(e) + m) / LAMBDAF;
    }
}

// ---------------------------------------------------------------------------
extern "C" void kernel_launch(void* const* d_in, const int* in_sizes, int n_in,
                              void* d_out, int out_size)
{
    const float* images   = (const float*)d_in[0];  // (64, 36, 1024)
    const float* captions = (const float*)d_in[1];  // (64, 32, 1024)
    const int*   cap_lens = (const int*)  d_in[2];  // (64,)
    const float* W_g      = (const float*)d_in[3];  // (1024, 1024)
    float* out = (float*)d_out;                     // (64, 64)

    __half *pA2, *pB2, *pBW;
    float *pX;
    cudaGetSymbolAddress((void**)&pA2, g_A2);
    cudaGetSymbolAddress((void**)&pB2, g_B2);
    cudaGetSymbolAddress((void**)&pBW, g_BW);
    cudaGetSymbolAddress((void**)&pX,  g_X);

    // P variant: BM=64, BN=128, warps 1x2 (64 thr), warp tile 64x64.
    //            smem = 3*(64+128)*128 + 1024 = 74752 -> up to 3 CTAs/SM
    // X variant: BM=128, BN=128, warps 2x2 (128 thr), warp tile 64x64.
    //            smem = 3*(128+128)*128 + 1024 = 99328 -> 2 CTAs/SM
    const int SMEM_P = NSTAGE * (64 + 128) * 128 + 1024;
    const int SMEM_X = NSTAGE * (128 + 128) * 128 + 1024;
    cudaFuncSetAttribute((const void*)gemm_mma_kernel<64, 128, 1, 2, 2>,
                         cudaFuncAttributeMaxDynamicSharedMemorySize, SMEM_P);
    cudaFuncSetAttribute((const void*)gemm_mma_kernel<128, 128, 2, 2, 2>,
                         cudaFuncAttributeMaxDynamicSharedMemorySize, SMEM_X);

    // 1) Splits
    split_rows_kernel<<<MROWS * DD / 256, 256>>>(images, pA2, 1);     // [hi|lo]
    split_rows_kernel<<<CROWS * DD / 256, 256>>>(captions, pB2, 0);   // [hi|hi]
    {
        dim3 grid(DD / 32, DD / 32);
        split_w_kernel<<<grid, dim3(32, 32)>>>(W_g);                  // [hi|hi]
    }

    // 2) GEMM-P: Y = images @ W_g(hi) -> split fp16 [hi|lo] into g_A2 rows [2304, 4608)
    //    grid (8, 36) = 288 CTAs, 64 threads
    {
        dim3 grid(DD / 128, MROWS / 64);
        gemm_mma_kernel<64, 128, 1, 2, 2><<<grid, 64, SMEM_P>>>(pA2, pBW, nullptr,
                                                                pA2 + (size_t)MROWS * KSPLIT, 1, 0);
    }
    // 3) GEMM-X: X = [images ; Y] @ captions^T  (4608 x 2048, fp32)
    //    grid (16, 36) = 576 CTAs, 128 threads, 2 CTAs/SM
    {
        dim3 grid(XCOLS / 128, AROWS / 128);
        gemm_mma_kernel<128, 128, 2, 2, 2><<<grid, 128, SMEM_X>>>(pA2, pB2, pX, nullptr, 0, XCOLS);
    }

    // 4) Gram + caption norms
    gram_kernel<<<NB, 256>>>(images);
    w1_kernel<<<CROWS / 8, 256>>>(captions);

    // 5) Final epilogue
    {
        dim3 grid(NB, NB);
        epilogue_kernel<<<grid, 128>>>(cap_lens, out);
    }
}

// round 10
// speedup vs baseline: 1.0112x; 1.0112x over previous
#include <cuda_runtime.h>
#include <cuda_fp16.h>
#include <math_constants.h>
#include <cstdint>

// Problem constants
#define DD     1024
#define NB     64
#define SS     36
#define LL     32
#define SMOOTHF 9.0f
#define LAMBDAF 6.0f
#define EPSF   1e-8f

#define MROWS  (NB*SS)       // 2304 image rows
#define CROWS  (NB*LL)       // 2048 caption rows
#define AROWS  (2*MROWS)     // 4608 = [images ; Y]
#define KSPLIT 2048          // K after fp16 [hi|lo] (A-side) / [hi|hi] (B-side) concat
#define XCOLS  CROWS         // 2048

#define BK 64                        // fp16 elems per chunk = 128 B rows
#define NCHUNK (KSPLIT / BK)         // 32
#define NSTAGE 3

// Scratch (static device globals; allocation forbidden)
__device__ __half g_A2[(size_t)AROWS * KSPLIT];  // [images-split ; Y-split]
__device__ __half g_B2[(size_t)CROWS * KSPLIT];  // captions split
__device__ __half g_BW[(size_t)DD   * KSPLIT];   // W_g^T split
__device__ float g_X[(size_t)AROWS * XCOLS];     // fused GEMM output fp32
__device__ float g_G[NB * SS * SS];
__device__ float g_w1[CROWS];

// ---------------------------------------------------------------------------
// PTX helpers (base-ISA only: cp.async, ldmatrix, mma.sync)
// ---------------------------------------------------------------------------
__device__ __forceinline__ uint32_t smem_u32(const void* p) {
    uint32_t a;
    asm("{ .reg .u64 t; cvta.to.shared.u64 t, %1; cvt.u32.u64 %0, t; }" : "=r"(a) : "l"(p));
    return a;
}
#define CP_ASYNC16(dst, src) \
    asm volatile("cp.async.cg.shared.global [%0], [%1], 16;\n" :: "r"(dst), "l"(src))
#define CP_COMMIT() asm volatile("cp.async.commit_group;\n" ::: "memory")
#define CP_WAIT(n)  asm volatile("cp.async.wait_group %0;\n" :: "n"(n) : "memory")

__device__ __forceinline__ void ldsm4(uint32_t* r, uint32_t addr) {
    asm volatile("ldmatrix.sync.aligned.m8n8.x4.shared.b16 {%0,%1,%2,%3}, [%4];"
                 : "=r"(r[0]), "=r"(r[1]), "=r"(r[2]), "=r"(r[3]) : "r"(addr));
}
__device__ __forceinline__ void mma16816(float* c, const uint32_t* a,
                                         uint32_t b0, uint32_t b1) {
    asm volatile("mma.sync.aligned.m16n8k16.row.col.f32.f16.f16.f32 "
                 "{%0,%1,%2,%3}, {%4,%5,%6,%7}, {%8,%9}, {%0,%1,%2,%3};"
                 : "+f"(c[0]), "+f"(c[1]), "+f"(c[2]), "+f"(c[3])
                 : "r"(a[0]), "r"(a[1]), "r"(a[2]), "r"(a[3]), "r"(b0), "r"(b1));
}
// SW128 swizzle for 128B rows
__device__ __forceinline__ uint32_t swz(int row, int seg) {
    return (uint32_t)(row * 128 + (seg ^ ((row & 7) << 4)));
}

// ---------------------------------------------------------------------------
// Split kernels (fp16 two-term)
// A-side pattern: [hi | lo]; B-side pattern: [hi | hi]
// ---------------------------------------------------------------------------
__global__ void split_rows_kernel(const float* __restrict__ src, __half* __restrict__ dst,
                                  int second_is_lo)
{
    int idx = blockIdx.x * 256 + threadIdx.x;
    int row = idx >> 10, col = idx & 1023;
    float f = src[idx];
    __half hi = __float2half(f);
    __half sec = second_is_lo ? __float2half(f - __half2float(hi)) : hi;
    size_t r = (size_t)row * KSPLIT;
    dst[r + col] = hi;
    dst[r + 1024 + col] = sec;
}

// W_g transpose + split (B-side [hi|hi]): g_BW[n][k] = W_g[k][n]
__global__ void split_w_kernel(const float* __restrict__ W)
{
    __shared__ float t[32][33];
    int k0 = blockIdx.y * 32, n0 = blockIdx.x * 32;
    int tx = threadIdx.x, ty = threadIdx.y;
    t[ty][tx] = W[(size_t)(k0 + ty) * DD + n0 + tx];
    __syncthreads();
    float f = t[tx][ty];                       // = W[k0+tx][n0+ty]
    __half hi = __float2half(f);
    size_t r = (size_t)(n0 + ty) * KSPLIT;
    g_BW[r + k0 + tx] = hi;
    g_BW[r + 1024 + k0 + tx] = hi;
}

// ---------------------------------------------------------------------------
// HMMA NT GEMM: C[m,n] = sum_k A[m,k]*B[n,k], K = KSPLIT.
// Templated tile / warp layout; 3-stage cp.async, single-buffered fragments.
// mode 0: write fp32 C (ldc). mode 1: write split fp16 rows [hi|lo] into Aout.
// ---------------------------------------------------------------------------
template<int BM, int BN, int WARPS_M, int WARPS_N, int MIN_CTAS>
__global__ __launch_bounds__(WARPS_M * WARPS_N * 32, MIN_CTAS)
void gemm_mma_kernel(const __half* __restrict__ A,
                     const __half* __restrict__ B,
                     float* __restrict__ C,
                     __half* __restrict__ Aout,
                     int mode, int ldc)
{
    constexpr int THREADS = WARPS_M * WARPS_N * 32;
    constexpr int MT  = BM / WARPS_M / 16;   // A 16-row subtiles per warp
    constexpr int NT2 = BN / WARPS_N / 16;   // B 16-row ldsm tiles per warp
    constexpr int NJ  = NT2 * 2;             // n8 column groups per warp
    constexpr int A_BYTES = BM * 128;
    constexpr int B_BYTES = BN * 128;
    constexpr int STAGE_BYTES = A_BYTES + B_BYTES;
    constexpr int A_IT = BM * 8 / THREADS;
    constexpr int B_IT = BN * 8 / THREADS;

    extern __shared__ char smem_raw[];
    const uint32_t sbase = (smem_u32(smem_raw) + 1023u) & ~1023u;

    const int tid = threadIdx.x;
    const int wid = tid >> 5, lane = tid & 31;
    const int wm = wid / WARPS_N;
    const int wn = wid % WARPS_N;
    const size_t arow0 = (size_t)blockIdx.y * BM;
    const size_t brow0 = (size_t)blockIdx.x * BN;

    const int lr = lane & 15;
    const int lseg = (lane >> 4) * 16;

    float acc[MT][NJ][4];
#pragma unroll
    for (int mt = 0; mt < MT; mt++)
#pragma unroll
        for (int j = 0; j < NJ; j++)
#pragma unroll
            for (int e = 0; e < 4; e++) acc[mt][j][e] = 0.f;

    uint32_t af[MT][4], bf[NT2][4];

    const char* Abase = (const char*)(A + arow0 * KSPLIT);
    const char* Bbase = (const char*)(B + brow0 * KSPLIT);
    auto load_chunk = [&](int c, int s) {
        const uint32_t sA = sbase + s * STAGE_BYTES;
        const uint32_t sB = sA + A_BYTES;
        const size_t cb = (size_t)c * 128;
#pragma unroll
        for (int i = 0; i < A_IT; i++) {
            int p = tid + i * THREADS;
            int r = p >> 3, seg = (p & 7) * 16;
            CP_ASYNC16(sA + swz(r, seg), Abase + (size_t)r * (KSPLIT * 2) + cb + seg);
        }
#pragma unroll
        for (int i = 0; i < B_IT; i++) {
            int p = tid + i * THREADS;
            int r = p >> 3, seg = (p & 7) * 16;
            CP_ASYNC16(sB + swz(r, seg), Bbase + (size_t)r * (KSPLIT * 2) + cb + seg);
        }
        CP_COMMIT();
    };

    load_chunk(0, 0);
    load_chunk(1, 1);

    for (int c = 0; c < NCHUNK; c++) {
        // Ensure chunk c complete (committed >=2 iterations ago).
        if (c + 1 < NCHUNK) { CP_WAIT(1); } else { CP_WAIT(0); }
        __syncthreads();   // visibility of chunk c; all warps done with stage (c+2)%3's old tenant
        if (c + 2 < NCHUNK) load_chunk(c + 2, (c + 2) % NSTAGE);
        const int s = c % NSTAGE;
        const uint32_t sA = sbase + s * STAGE_BYTES;
        const uint32_t sB = sA + A_BYTES;
#pragma unroll
        for (int kk = 0; kk < 4; kk++) {
#pragma unroll
            for (int mt = 0; mt < MT; mt++)
                ldsm4(af[mt], sA + swz(wm * (MT * 16) + mt * 16 + lr, kk * 32 + lseg));
#pragma unroll
            for (int nt = 0; nt < NT2; nt++)
                ldsm4(bf[nt], sB + swz(wn * (NT2 * 16) + nt * 16 + lr, kk * 32 + lseg));
#pragma unroll
            for (int mt = 0; mt < MT; mt++)
#pragma unroll
                for (int nt = 0; nt < NT2; nt++)
#pragma unroll
                    for (int h = 0; h < 2; h++)
                        mma16816(acc[mt][nt * 2 + h], af[mt], bf[nt][h], bf[nt][h + 2]);
        }
    }

    // Epilogue. C-frag mapping: lane l -> rows (l>>2, l>>2+8), cols 2*(l&3)+{0,1}.
    const int r0 = lane >> 2;
    const int cb2 = 2 * (lane & 3);
    if (mode == 0) {
#pragma unroll
        for (int mt = 0; mt < MT; mt++) {
#pragma unroll
            for (int j = 0; j < NJ; j++) {
                size_t row = arow0 + wm * (MT * 16) + mt * 16 + r0;
                size_t col = brow0 + wn * (NJ * 8) + j * 8 + cb2;
                *(float2*)(C + row * ldc + col)       = make_float2(acc[mt][j][0], acc[mt][j][1]);
                *(float2*)(C + (row + 8) * ldc + col) = make_float2(acc[mt][j][2], acc[mt][j][3]);
            }
        }
    } else {
#pragma unroll
        for (int mt = 0; mt < MT; mt++) {
#pragma unroll
            for (int j = 0; j < NJ; j++) {
                int col = (int)brow0 + wn * (NJ * 8) + j * 8 + cb2;   // < 1024
#pragma unroll
                for (int h = 0; h < 2; h++) {
                    size_t row = arow0 + wm * (MT * 16) + mt * 16 + r0 + h * 8;
                    __half* dr = Aout + row * KSPLIT;
                    float f0 = acc[mt][j][2 * h], f1 = acc[mt][j][2 * h + 1];
                    __half h0 = __float2half(f0);
                    __half h1 = __float2half(f1);
                    __half l0 = __float2half(f0 - __half2float(h0));
                    __half l1 = __float2half(f1 - __half2float(h1));
                    __half2 hv; hv.x = h0; hv.y = h1;
                    __half2 lv; lv.x = l0; lv.y = l1;
                    *(__half2*)(dr + col)        = hv;   // [hi | lo]
                    *(__half2*)(dr + 1024 + col) = lv;
                }
            }
        }
    }
}

// ---------------------------------------------------------------------------
// Per-image Gram matrix
// ---------------------------------------------------------------------------
__global__ void gram_kernel(const float* __restrict__ images)
{
    __shared__ float T[SS][65];
    const int b = blockIdx.x;
    const int tid = threadIdx.x;
    float acc[6] = {0.f, 0.f, 0.f, 0.f, 0.f, 0.f};
    for (int d0 = 0; d0 < DD; d0 += 64) {
        __syncthreads();
        for (int i = tid; i < SS * 64; i += 256) {
            int r = i / 64, c = i % 64;
            T[r][c] = images[((size_t)b * SS + r) * DD + d0 + c];
        }
        __syncthreads();
#pragma unroll
        for (int pi = 0; pi < 6; pi++) {
            int p = tid + pi * 256;
            if (p < SS * SS) {
                int s = p / SS, s2 = p % SS;
                float sum = 0.f;
#pragma unroll
                for (int k = 0; k < 64; k++) sum += T[s][k] * T[s2][k];
                acc[pi] += sum;
            }
        }
    }
#pragma unroll
    for (int pi = 0; pi < 6; pi++) {
        int p = tid + pi * 256;
        if (p < SS * SS) g_G[b * SS * SS + p] = acc[pi];
    }
}

__global__ void w1_kernel(const float* __restrict__ captions)
{
    const int row = blockIdx.x * 8 + (threadIdx.x >> 5);
    const int lane = threadIdx.x & 31;
    const float* p = captions + (size_t)row * DD;
    float s = 0.f;
    for (int k = lane; k < DD; k += 32) { float v = p[k]; s += v * v; }
#pragma unroll
    for (int o = 16; o; o >>= 1) s += __shfl_xor_sync(0xffffffffu, s, o);
    if (lane == 0) g_w1[row] = sqrtf(s);
}

// ---------------------------------------------------------------------------
// Final epilogue: one block per (caption i, image b)
// ---------------------------------------------------------------------------
__global__ __launch_bounds__(128)
void epilogue_kernel(const int* __restrict__ cap_lens, float* __restrict__ out)
{
    const int i = blockIdx.x;
    const int b = blockIdx.y;

    __shared__ float sA[SS][LL];
    __shared__ float sC[SS][LL];
    __shared__ float sQ[SS][LL];
    __shared__ float sG[SS][SS];
    __shared__ float snorm[SS];

    const int tid = threadIdx.x;
    const int len = cap_lens[i];

    for (int p = tid; p < SS * SS; p += 128)
        sG[p / SS][p % SS] = g_G[b * SS * SS + p];

    for (int p = tid; p < SS * LL; p += 128) {
        int s = p / LL, l = p % LL;
        size_t col = (size_t)i * LL + l;
        float a = g_X[(size_t)(MROWS + b * SS + s) * XCOLS + col];  // attn logits (Y.cap)
        a = (a > 0.f) ? a : 0.1f * a;
        if (l >= len) a = 0.f;
        sA[s][l] = a;
        sC[s][l] = g_X[(size_t)(b * SS + s) * XCOLS + col];          // cap . img
    }
    __syncthreads();

    if (tid < SS) {
        float s2 = 0.f;
#pragma unroll
        for (int l = 0; l < LL; l++) { float v = sA[tid][l]; s2 += v * v; }
        snorm[tid] = 1.f / (sqrtf(s2) + EPSF);
    }
    __syncthreads();

    if (tid < LL) {
        const int l = tid;
        float vals[SS];
        float m = -CUDART_INF_F;
#pragma unroll
        for (int s = 0; s < SS; s++) {
            float v = sA[s][l] * snorm[s] * SMOOTHF;
            vals[s] = v;
            m = fmaxf(m, v);
        }
        float sum = 0.f;
#pragma unroll
        for (int s = 0; s < SS; s++) {
            float e = expf(vals[s] - m);
            vals[s] = e;
            sum += e;
        }
        float inv = 1.f / sum;
#pragma unroll
        for (int s = 0; s < SS; s++) sA[s][l] = vals[s] * inv;
    }
    __syncthreads();

    for (int p = tid; p < SS * LL; p += 128) {
        int s = p / LL, l = p % LL;
        float sum = 0.f;
#pragma unroll
        for (int s2 = 0; s2 < SS; s2++) sum += sG[s][s2] * sA[s2][l];
        sQ[s][l] = sum;
    }
    __syncthreads();

    if (tid < LL) {
        const int l = tid;
        float w12 = 0.f, w2q = 0.f;
#pragma unroll
        for (int s = 0; s < SS; s++) {
            float p = sA[s][l];
            w12 += p * sC[s][l];
            w2q += p * sQ[s][l];
        }
        float w2 = sqrtf(fmaxf(w2q, 0.f));
        float w1 = g_w1[i * LL + l];
        float r = w12 / fmaxf(w1 * w2, EPSF);

        float z = (l < len) ? r * LAMBDAF : -CUDART_INF_F;
        float m = z;
#pragma unroll
        for (int o = 16; o; o >>= 1) m = fmaxf(m, __shfl_xor_sync(0xffffffffu, m, o));
        float e = (l < len) ? expf(z - m) : 0.f;
#pragma unroll
        for (int o = 16; o; o >>= 1) e += __shfl_xor_sync(0xffffffffu, e, o);
        if (l == 0) out[b * NB + i] = (logf(e) + m) / LAMBDAF;
    }
}

// ---------------------------------------------------------------------------
extern "C" void kernel_launch(void* const* d_in, const int* in_sizes, int n_in,
                              void* d_out, int out_size)
{
    const float* images   = (const float*)d_in[0];  // (64, 36, 1024)
    const float* captions = (const float*)d_in[1];  // (64, 32, 1024)
    const int*   cap_lens = (const int*)  d_in[2];  // (64,)
    const float* W_g      = (const float*)d_in[3];  // (1024, 1024)
    float* out = (float*)d_out;                     // (64, 64)

    __half *pA2, *pB2, *pBW;
    float *pX;
    cudaGetSymbolAddress((void**)&pA2, g_A2);
    cudaGetSymbolAddress((void**)&pB2, g_B2);
    cudaGetSymbolAddress((void**)&pBW, g_BW);
    cudaGetSymbolAddress((void**)&pX,  g_X);

    // P variant: BM=64, BN=64, warps 2x2 (128 thr), warp tile 32x32, 4 CTAs/SM.
    //            smem = 3*(64+64)*128 + 1024 = 50176; grid (16,36)=576
    // X variant: BM=128, BN=256, warps 2x4 (256 thr), warp tile 64x64, 1 CTA/SM.
    //            smem = 3*(128+256)*128 + 1024 = 148480; grid (8,36)=288
    const int SMEM_P = NSTAGE * (64 + 64) * 128 + 1024;
    const int SMEM_X = NSTAGE * (128 + 256) * 128 + 1024;
    cudaFuncSetAttribute((const void*)gemm_mma_kernel<64, 64, 2, 2, 4>,
                         cudaFuncAttributeMaxDynamicSharedMemorySize, SMEM_P);
    cudaFuncSetAttribute((const void*)gemm_mma_kernel<128, 256, 2, 4, 1>,
                         cudaFuncAttributeMaxDynamicSharedMemorySize, SMEM_X);

    // 1) Splits
    split_rows_kernel<<<MROWS * DD / 256, 256>>>(images, pA2, 1);     // [hi|lo]
    split_rows_kernel<<<CROWS * DD / 256, 256>>>(captions, pB2, 0);   // [hi|hi]
    {
        dim3 grid(DD / 32, DD / 32);
        split_w_kernel<<<grid, dim3(32, 32)>>>(W_g);                  // [hi|hi]
    }

    // 2) GEMM-P: Y = images @ W_g(hi) -> split fp16 [hi|lo] into g_A2 rows [2304, 4608)
    //    grid (16, 36) = 576 CTAs, 128 threads, 4 CTAs/SM
    {
        dim3 grid(DD / 64, MROWS / 64);
        gemm_mma_kernel<64, 64, 2, 2, 4><<<grid, 128, SMEM_P>>>(pA2, pBW, nullptr,
                                                                pA2 + (size_t)MROWS * KSPLIT, 1, 0);
    }
    // 3) GEMM-X: X = [images ; Y] @ captions^T  (4608 x 2048, fp32)
    //    grid (8, 36) = 288 CTAs, 256 threads, 1 CTA/SM, 64x64 warp tiles
    {
        dim3 grid(XCOLS / 256, AROWS / 128);
        gemm_mma_kernel<128, 256, 2, 4, 1><<<grid, 256, SMEM_X>>>(pA2, pB2, pX, nullptr, 0, XCOLS);
    }

    // 4) Gram + caption norms
    gram_kernel<<<NB, 256>>>(images);
    w1_kernel<<<CROWS / 8, 256>>>(captions);

    // 5) Final epilogue
    {
        dim3 grid(NB, NB);
        epilogue_kernel<<<grid, 128>>>(cap_lens, out);
    }
}

// round 11
// speedup vs baseline: 1.3309x; 1.3162x over previous
#include <cuda_runtime.h>
#include <cuda_fp16.h>
#include <math_constants.h>
#include <cstdint>

// Problem constants
#define DD     1024
#define NB     64
#define SS     36
#define LL     32
#define SMOOTHF 9.0f
#define LAMBDAF 6.0f
#define EPSF   1e-8f

#define MROWS  (NB*SS)       // 2304 image rows
#define CROWS  (NB*LL)       // 2048 caption rows
#define AROWS  (2*MROWS)     // 4608 = [images ; Y]
#define KSPLIT 1024          // plain fp16, no splitting
#define XCOLS  CROWS         // 2048

#define BK 64                        // fp16 elems per chunk = 128 B rows
#define NCHUNK (KSPLIT / BK)         // 16
#define NSTAGE 3

// Scratch (static device globals; allocation forbidden)
__device__ __half g_A2[(size_t)AROWS * KSPLIT];  // [images_h ; Y_h]   9.4MB
__device__ __half g_B2[(size_t)CROWS * KSPLIT];  // captions_h         4.2MB
__device__ __half g_BW[(size_t)DD   * KSPLIT];   // W_g^T fp16         2.1MB
__device__ float g_X[(size_t)AROWS * XCOLS];     // fused GEMM output fp32
__device__ float g_G[NB * SS * SS];
__device__ float g_w1[CROWS];

// ---------------------------------------------------------------------------
// PTX helpers (base-ISA only: cp.async, ldmatrix, mma.sync)
// ---------------------------------------------------------------------------
__device__ __forceinline__ uint32_t smem_u32(const void* p) {
    uint32_t a;
    asm("{ .reg .u64 t; cvta.to.shared.u64 t, %1; cvt.u32.u64 %0, t; }" : "=r"(a) : "l"(p));
    return a;
}
#define CP_ASYNC16(dst, src) \
    asm volatile("cp.async.cg.shared.global [%0], [%1], 16;\n" :: "r"(dst), "l"(src))
#define CP_COMMIT() asm volatile("cp.async.commit_group;\n" ::: "memory")
#define CP_WAIT(n)  asm volatile("cp.async.wait_group %0;\n" :: "n"(n) : "memory")

__device__ __forceinline__ void ldsm4(uint32_t* r, uint32_t addr) {
    asm volatile("ldmatrix.sync.aligned.m8n8.x4.shared.b16 {%0,%1,%2,%3}, [%4];"
                 : "=r"(r[0]), "=r"(r[1]), "=r"(r[2]), "=r"(r[3]) : "r"(addr));
}
__device__ __forceinline__ void mma16816(float* c, const uint32_t* a,
                                         uint32_t b0, uint32_t b1) {
    asm volatile("mma.sync.aligned.m16n8k16.row.col.f32.f16.f16.f32 "
                 "{%0,%1,%2,%3}, {%4,%5,%6,%7}, {%8,%9}, {%0,%1,%2,%3};"
                 : "+f"(c[0]), "+f"(c[1]), "+f"(c[2]), "+f"(c[3])
                 : "r"(a[0]), "r"(a[1]), "r"(a[2]), "r"(a[3]), "r"(b0), "r"(b1));
}
// SW128 swizzle for 128B rows
__device__ __forceinline__ uint32_t swz(int row, int seg) {
    return (uint32_t)(row * 128 + (seg ^ ((row & 7) << 4)));
}

// ---------------------------------------------------------------------------
// Convert kernels: fp32 -> fp16 (vectorized, layout-preserving)
// ---------------------------------------------------------------------------
__global__ void cvt_h_kernel(const float* __restrict__ src, __half* __restrict__ dst)
{
    int i = blockIdx.x * 256 + threadIdx.x;          // element-pair index
    float2 v = *(const float2*)(src + 2 * i);
    __half2 h; h.x = __float2half(v.x); h.y = __float2half(v.y);
    *(__half2*)(dst + 2 * i) = h;
}

// W_g transpose to fp16: g_BW[n][k] = W_g[k][n]
__global__ void cvt_w_kernel(const float* __restrict__ W)
{
    __shared__ float t[32][33];
    int k0 = blockIdx.y * 32, n0 = blockIdx.x * 32;
    int tx = threadIdx.x, ty = threadIdx.y;
    t[ty][tx] = W[(size_t)(k0 + ty) * DD + n0 + tx];
    __syncthreads();
    g_BW[(size_t)(n0 + ty) * KSPLIT + k0 + tx] = __float2half(t[tx][ty]);
}

// ---------------------------------------------------------------------------
// HMMA NT GEMM: C[m,n] = sum_k A[m,k]*B[n,k], K = KSPLIT.
// Templated tile / warp layout; 3-stage cp.async, single-buffered fragments.
// mode 0: write fp32 C (ldc). mode 1: write fp16 rows into Aout.
// ---------------------------------------------------------------------------
template<int BM, int BN, int WARPS_M, int WARPS_N, int MIN_CTAS>
__global__ __launch_bounds__(WARPS_M * WARPS_N * 32, MIN_CTAS)
void gemm_mma_kernel(const __half* __restrict__ A,
                     const __half* __restrict__ B,
                     float* __restrict__ C,
                     __half* __restrict__ Aout,
                     int mode, int ldc)
{
    constexpr int THREADS = WARPS_M * WARPS_N * 32;
    constexpr int MT  = BM / WARPS_M / 16;   // A 16-row subtiles per warp
    constexpr int NT2 = BN / WARPS_N / 16;   // B 16-row ldsm tiles per warp
    constexpr int NJ  = NT2 * 2;             // n8 column groups per warp
    constexpr int A_BYTES = BM * 128;
    constexpr int B_BYTES = BN * 128;
    constexpr int STAGE_BYTES = A_BYTES + B_BYTES;
    constexpr int A_IT = BM * 8 / THREADS;
    constexpr int B_IT = BN * 8 / THREADS;

    extern __shared__ char smem_raw[];
    const uint32_t sbase = (smem_u32(smem_raw) + 1023u) & ~1023u;

    const int tid = threadIdx.x;
    const int wid = tid >> 5, lane = tid & 31;
    const int wm = wid / WARPS_N;
    const int wn = wid % WARPS_N;
    const size_t arow0 = (size_t)blockIdx.y * BM;
    const size_t brow0 = (size_t)blockIdx.x * BN;

    const int lr = lane & 15;
    const int lseg = (lane >> 4) * 16;

    float acc[MT][NJ][4];
#pragma unroll
    for (int mt = 0; mt < MT; mt++)
#pragma unroll
        for (int j = 0; j < NJ; j++)
#pragma unroll
            for (int e = 0; e < 4; e++) acc[mt][j][e] = 0.f;

    uint32_t af[MT][4], bf[NT2][4];

    const char* Abase = (const char*)(A + arow0 * KSPLIT);
    const char* Bbase = (const char*)(B + brow0 * KSPLIT);
    auto load_chunk = [&](int c, int s) {
        const uint32_t sA = sbase + s * STAGE_BYTES;
        const uint32_t sB = sA + A_BYTES;
        const size_t cb = (size_t)c * 128;
#pragma unroll
        for (int i = 0; i < A_IT; i++) {
            int p = tid + i * THREADS;
            int r = p >> 3, seg = (p & 7) * 16;
            CP_ASYNC16(sA + swz(r, seg), Abase + (size_t)r * (KSPLIT * 2) + cb + seg);
        }
#pragma unroll
        for (int i = 0; i < B_IT; i++) {
            int p = tid + i * THREADS;
            int r = p >> 3, seg = (p & 7) * 16;
            CP_ASYNC16(sB + swz(r, seg), Bbase + (size_t)r * (KSPLIT * 2) + cb + seg);
        }
        CP_COMMIT();
    };

    load_chunk(0, 0);
    load_chunk(1, 1);

    for (int c = 0; c < NCHUNK; c++) {
        // Ensure chunk c complete (committed >=2 iterations ago).
        if (c + 1 < NCHUNK) { CP_WAIT(1); } else { CP_WAIT(0); }
        __syncthreads();   // visibility of chunk c; all warps done with stage (c+2)%3's old tenant
        if (c + 2 < NCHUNK) load_chunk(c + 2, (c + 2) % NSTAGE);
        const int s = c % NSTAGE;
        const uint32_t sA = sbase + s * STAGE_BYTES;
        const uint32_t sB = sA + A_BYTES;
#pragma unroll
        for (int kk = 0; kk < 4; kk++) {
#pragma unroll
            for (int mt = 0; mt < MT; mt++)
                ldsm4(af[mt], sA + swz(wm * (MT * 16) + mt * 16 + lr, kk * 32 + lseg));
#pragma unroll
            for (int nt = 0; nt < NT2; nt++)
                ldsm4(bf[nt], sB + swz(wn * (NT2 * 16) + nt * 16 + lr, kk * 32 + lseg));
#pragma unroll
            for (int mt = 0; mt < MT; mt++)
#pragma unroll
                for (int nt = 0; nt < NT2; nt++)
#pragma unroll
                    for (int h = 0; h < 2; h++)
                        mma16816(acc[mt][nt * 2 + h], af[mt], bf[nt][h], bf[nt][h + 2]);
        }
    }

    // Epilogue. C-frag mapping: lane l -> rows (l>>2, l>>2+8), cols 2*(l&3)+{0,1}.
    const int r0 = lane >> 2;
    const int cb2 = 2 * (lane & 3);
    if (mode == 0) {
#pragma unroll
        for (int mt = 0; mt < MT; mt++) {
#pragma unroll
            for (int j = 0; j < NJ; j++) {
                size_t row = arow0 + wm * (MT * 16) + mt * 16 + r0;
                size_t col = brow0 + wn * (NJ * 8) + j * 8 + cb2;
                *(float2*)(C + row * ldc + col)       = make_float2(acc[mt][j][0], acc[mt][j][1]);
                *(float2*)(C + (row + 8) * ldc + col) = make_float2(acc[mt][j][2], acc[mt][j][3]);
            }
        }
    } else {
#pragma unroll
        for (int mt = 0; mt < MT; mt++) {
#pragma unroll
            for (int j = 0; j < NJ; j++) {
                int col = (int)brow0 + wn * (NJ * 8) + j * 8 + cb2;   // < 1024
#pragma unroll
                for (int h = 0; h < 2; h++) {
                    size_t row = arow0 + wm * (MT * 16) + mt * 16 + r0 + h * 8;
                    __half* dr = Aout + row * KSPLIT;
                    __half2 hv;
                    hv.x = __float2half(acc[mt][j][2 * h]);
                    hv.y = __float2half(acc[mt][j][2 * h + 1]);
                    *(__half2*)(dr + col) = hv;
                }
            }
        }
    }
}

// ---------------------------------------------------------------------------
// Per-image Gram matrix
// ---------------------------------------------------------------------------
__global__ void gram_kernel(const float* __restrict__ images)
{
    __shared__ float T[SS][65];
    const int b = blockIdx.x;
    const int tid = threadIdx.x;
    float acc[6] = {0.f, 0.f, 0.f, 0.f, 0.f, 0.f};
    for (int d0 = 0; d0 < DD; d0 += 64) {
        __syncthreads();
        for (int i = tid; i < SS * 64; i += 256) {
            int r = i / 64, c = i % 64;
            T[r][c] = images[((size_t)b * SS + r) * DD + d0 + c];
        }
        __syncthreads();
#pragma unroll
        for (int pi = 0; pi < 6; pi++) {
            int p = tid + pi * 256;
            if (p < SS * SS) {
                int s = p / SS, s2 = p % SS;
                float sum = 0.f;
#pragma unroll
                for (int k = 0; k < 64; k++) sum += T[s][k] * T[s2][k];
                acc[pi] += sum;
            }
        }
    }
#pragma unroll
    for (int pi = 0; pi < 6; pi++) {
        int p = tid + pi * 256;
        if (p < SS * SS) g_G[b * SS * SS + p] = acc[pi];
    }
}

__global__ void w1_kernel(const float* __restrict__ captions)
{
    const int row = blockIdx.x * 8 + (threadIdx.x >> 5);
    const int lane = threadIdx.x & 31;
    const float* p = captions + (size_t)row * DD;
    float s = 0.f;
    for (int k = lane; k < DD; k += 32) { float v = p[k]; s += v * v; }
#pragma unroll
    for (int o = 16; o; o >>= 1) s += __shfl_xor_sync(0xffffffffu, s, o);
    if (lane == 0) g_w1[row] = sqrtf(s);
}

// ---------------------------------------------------------------------------
// Final epilogue: one block per (caption i, image b)
// ---------------------------------------------------------------------------
__global__ __launch_bounds__(128)
void epilogue_kernel(const int* __restrict__ cap_lens, float* __restrict__ out)
{
    const int i = blockIdx.x;
    const int b = blockIdx.y;

    __shared__ float sA[SS][LL];
    __shared__ float sC[SS][LL];
    __shared__ float sQ[SS][LL];
    __shared__ float sG[SS][SS];
    __shared__ float snorm[SS];

    const int tid = threadIdx.x;
    const int len = cap_lens[i];

    for (int p = tid; p < SS * SS; p += 128)
        sG[p / SS][p % SS] = g_G[b * SS * SS + p];

    for (int p = tid; p < SS * LL; p += 128) {
        int s = p / LL, l = p % LL;
        size_t col = (size_t)i * LL + l;
        float a = g_X[(size_t)(MROWS + b * SS + s) * XCOLS + col];  // attn logits (Y.cap)
        a = (a > 0.f) ? a : 0.1f * a;
        if (l >= len) a = 0.f;
        sA[s][l] = a;
        sC[s][l] = g_X[(size_t)(b * SS + s) * XCOLS + col];          // cap . img
    }
    __syncthreads();

    if (tid < SS) {
        float s2 = 0.f;
#pragma unroll
        for (int l = 0; l < LL; l++) { float v = sA[tid][l]; s2 += v * v; }
        snorm[tid] = 1.f / (sqrtf(s2) + EPSF);
    }
    __syncthreads();

    if (tid < LL) {
        const int l = tid;
        float vals[SS];
        float m = -CUDART_INF_F;
#pragma unroll
        for (int s = 0; s < SS; s++) {
            float v = sA[s][l] * snorm[s] * SMOOTHF;
            vals[s] = v;
            m = fmaxf(m, v);
        }
        float sum = 0.f;
#pragma unroll
        for (int s = 0; s < SS; s++) {
            float e = expf(vals[s] - m);
            vals[s] = e;
            sum += e;
        }
        float inv = 1.f / sum;
#pragma unroll
        for (int s = 0; s < SS; s++) sA[s][l] = vals[s] * inv;
    }
    __syncthreads();

    for (int p = tid; p < SS * LL; p += 128) {
        int s = p / LL, l = p % LL;
        float sum = 0.f;
#pragma unroll
        for (int s2 = 0; s2 < SS; s2++) sum += sG[s][s2] * sA[s2][l];
        sQ[s][l] = sum;
    }
    __syncthreads();

    if (tid < LL) {
        const int l = tid;
        float w12 = 0.f, w2q = 0.f;
#pragma unroll
        for (int s = 0; s < SS; s++) {
            float p = sA[s][l];
            w12 += p * sC[s][l];
            w2q += p * sQ[s][l];
        }
        float w2 = sqrtf(fmaxf(w2q, 0.f));
        float w1 = g_w1[i * LL + l];
        float r = w12 / fmaxf(w1 * w2, EPSF);

        float z = (l < len) ? r * LAMBDAF : -CUDART_INF_F;
        float m = z;
#pragma unroll
        for (int o = 16; o; o >>= 1) m = fmaxf(m, __shfl_xor_sync(0xffffffffu, m, o));
        float e = (l < len) ? expf(z - m) : 0.f;
#pragma unroll
        for (int o = 16; o; o >>= 1) e += __shfl_xor_sync(0xffffffffu, e, o);
        if (l == 0) out[b * NB + i] = (logf(e) + m) / LAMBDAF;
    }
}

// ---------------------------------------------------------------------------
extern "C" void kernel_launch(void* const* d_in, const int* in_sizes, int n_in,
                              void* d_out, int out_size)
{
    const float* images   = (const float*)d_in[0];  // (64, 36, 1024)
    const float* captions = (const float*)d_in[1];  // (64, 32, 1024)
    const int*   cap_lens = (const int*)  d_in[2];  // (64,)
    const float* W_g      = (const float*)d_in[3];  // (1024, 1024)
    float* out = (float*)d_out;                     // (64, 64)

    __half *pA2, *pB2, *pBW;
    float *pX;
    cudaGetSymbolAddress((void**)&pA2, g_A2);
    cudaGetSymbolAddress((void**)&pB2, g_B2);
    cudaGetSymbolAddress((void**)&pBW, g_BW);
    cudaGetSymbolAddress((void**)&pX,  g_X);

    // P variant: BM=64, BN=64, warps 2x2 (128 thr), 4 CTAs/SM.  smem = 50176; grid (16,36)
    // X variant: BM=128, BN=256, warps 2x4 (256 thr), 64x64 warp tiles, 1 CTA/SM.
    //            smem = 148480; grid (8,36)
    const int SMEM_P = NSTAGE * (64 + 64) * 128 + 1024;
    const int SMEM_X = NSTAGE * (128 + 256) * 128 + 1024;
    cudaFuncSetAttribute((const void*)gemm_mma_kernel<64, 64, 2, 2, 4>,
                         cudaFuncAttributeMaxDynamicSharedMemorySize, SMEM_P);
    cudaFuncSetAttribute((const void*)gemm_mma_kernel<128, 256, 2, 4, 1>,
                         cudaFuncAttributeMaxDynamicSharedMemorySize, SMEM_X);

    // 1) fp32 -> fp16 converts (layout-preserving) + W transpose
    cvt_h_kernel<<<MROWS * DD / 512, 256>>>(images, pA2);
    cvt_h_kernel<<<CROWS * DD / 512, 256>>>(captions, pB2);
    {
        dim3 grid(DD / 32, DD / 32);
        cvt_w_kernel<<<grid, dim3(32, 32)>>>(W_g);
    }

    // 2) GEMM-P: Y = images_h @ W_h -> fp16 into g_A2 rows [2304, 4608)
    {
        dim3 grid(DD / 64, MROWS / 64);
        gemm_mma_kernel<64, 64, 2, 2, 4><<<grid, 128, SMEM_P>>>(pA2, pBW, nullptr,
                                                                pA2 + (size_t)MROWS * KSPLIT, 1, 0);
    }
    // 3) GEMM-X: X = [images_h ; Y_h] @ captions_h^T  (4608 x 2048, fp32)
    {
        dim3 grid(XCOLS / 256, AROWS / 128);
        gemm_mma_kernel<128, 256, 2, 4, 1><<<grid, 256, SMEM_X>>>(pA2, pB2, pX, nullptr, 0, XCOLS);
    }

    // 4) Gram + caption norms (fp32 inputs, exact)
    gram_kernel<<<NB, 256>>>(images);
    w1_kernel<<<CROWS / 8, 256>>>(captions);

    // 5) Final epilogue
    {
        dim3 grid(NB, NB);
        epilogue_kernel<<<grid, 128>>>(cap_lens, out);
    }
}

// round 12
// speedup vs baseline: 1.3409x; 1.0075x over previous
#include <cuda_runtime.h>
#include <cuda_fp16.h>
#include <math_constants.h>
#include <cstdint>

// Problem constants
#define DD     1024
#define NB     64
#define SS     36
#define LL     32
#define SMOOTHF 9.0f
#define LAMBDAF 6.0f
#define EPSF   1e-8f

#define MROWS  (NB*SS)       // 2304 image rows
#define CROWS  (NB*LL)       // 2048 caption rows
#define AROWS  (2*MROWS)     // 4608 = [images ; Y]
#define KSPLIT 1024          // plain fp16
#define XCOLS  CROWS         // 2048

#define BK 64                        // fp16 elems per chunk = 128 B rows
#define NCHUNK (KSPLIT / BK)         // 16
#define NSTAGE 3

// Scratch (static device globals; allocation forbidden)
__device__ __half g_A2[(size_t)AROWS * KSPLIT];  // [images_h ; Y_h]
__device__ __half g_B2[(size_t)CROWS * KSPLIT];  // captions_h
__device__ __half g_BW[(size_t)DD   * KSPLIT];   // W_g^T fp16
__device__ float g_X[(size_t)AROWS * XCOLS];     // fused GEMM output fp32
__device__ float g_G[NB * SS * SS];
__device__ float g_w1[CROWS];

// ---------------------------------------------------------------------------
// PTX helpers (base-ISA only: cp.async, ldmatrix, mma.sync)
// ---------------------------------------------------------------------------
__device__ __forceinline__ uint32_t smem_u32(const void* p) {
    uint32_t a;
    asm("{ .reg .u64 t; cvta.to.shared.u64 t, %1; cvt.u32.u64 %0, t; }" : "=r"(a) : "l"(p));
    return a;
}
#define CP_ASYNC16(dst, src) \
    asm volatile("cp.async.cg.shared.global [%0], [%1], 16;\n" :: "r"(dst), "l"(src))
#define CP_COMMIT() asm volatile("cp.async.commit_group;\n" ::: "memory")
#define CP_WAIT(n)  asm volatile("cp.async.wait_group %0;\n" :: "n"(n) : "memory")

__device__ __forceinline__ void ldsm4(uint32_t* r, uint32_t addr) {
    asm volatile("ldmatrix.sync.aligned.m8n8.x4.shared.b16 {%0,%1,%2,%3}, [%4];"
                 : "=r"(r[0]), "=r"(r[1]), "=r"(r[2]), "=r"(r[3]) : "r"(addr));
}
__device__ __forceinline__ void mma16816(float* c, const uint32_t* a,
                                         uint32_t b0, uint32_t b1) {
    asm volatile("mma.sync.aligned.m16n8k16.row.col.f32.f16.f16.f32 "
                 "{%0,%1,%2,%3}, {%4,%5,%6,%7}, {%8,%9}, {%0,%1,%2,%3};"
                 : "+f"(c[0]), "+f"(c[1]), "+f"(c[2]), "+f"(c[3])
                 : "r"(a[0]), "r"(a[1]), "r"(a[2]), "r"(a[3]), "r"(b0), "r"(b1));
}
// SW128 swizzle for 128B rows
__device__ __forceinline__ uint32_t swz(int row, int seg) {
    return (uint32_t)(row * 128 + (seg ^ ((row & 7) << 4)));
}

// Fast exp on the FMA pipe (no MUFU): exp(x) = 2^(x*log2e), |rel err| ~2e-6.
// Valid for x in (-87, 20); NOT valid for -inf (callers guard masked lanes).
__device__ __forceinline__ float fexp(float x) {
    const float L2E = 1.4426950408889634f;
    float t = fmaf(x, L2E, 12582912.0f);          // round-to-nearest-int (magic)
    float i = t - 12582912.0f;
    float f = fmaf(x, L2E, -i);                   // frac in [-0.5, 0.5]
    float p = 1.3333558146e-3f;
    p = fmaf(p, f, 9.6181291076e-3f);
    p = fmaf(p, f, 5.5504108665e-2f);
    p = fmaf(p, f, 2.4022650696e-1f);
    p = fmaf(p, f, 6.9314718056e-1f);
    p = fmaf(p, f, 1.0f);
    return __int_as_float(__float_as_int(p) + (((int)i) << 23));
}

// ---------------------------------------------------------------------------
// Convert kernels: fp32 -> fp16 (vectorized, layout-preserving)
// images (MROWS*DD floats) then captions (CROWS*DD) in ONE launch.
// ---------------------------------------------------------------------------
#define IMG_PAIRS (MROWS * DD / 2)
__global__ void cvt_both_kernel(const float* __restrict__ images,
                                const float* __restrict__ captions,
                                __half* __restrict__ dimg, __half* __restrict__ dcap)
{
    int i = blockIdx.x * 256 + threadIdx.x;       // element-pair index
    const float* src; __half* dst; int j;
    if (i < IMG_PAIRS) { src = images;   dst = dimg; j = i; }
    else               { src = captions; dst = dcap; j = i - IMG_PAIRS; }
    float2 v = *(const float2*)(src + 2 * j);
    __half2 h; h.x = __float2half(v.x); h.y = __float2half(v.y);
    *(__half2*)(dst + 2 * j) = h;
}

// W_g transpose to fp16: g_BW[n][k] = W_g[k][n]
__global__ void cvt_w_kernel(const float* __restrict__ W)
{
    __shared__ float t[32][33];
    int k0 = blockIdx.y * 32, n0 = blockIdx.x * 32;
    int tx = threadIdx.x, ty = threadIdx.y;
    t[ty][tx] = W[(size_t)(k0 + ty) * DD + n0 + tx];
    __syncthreads();
    g_BW[(size_t)(n0 + ty) * KSPLIT + k0 + tx] = __float2half(t[tx][ty]);
}

// ---------------------------------------------------------------------------
// HMMA NT GEMM: C[m,n] = sum_k A[m,k]*B[n,k], K = KSPLIT.
// 3-stage cp.async; REGISTER DOUBLE-BUFFERED fragments (ldsm kk+1 overlaps mma kk).
// mode 0: write fp32 C (ldc). mode 1: write fp16 rows into Aout.
// ---------------------------------------------------------------------------
template<int BM, int BN, int WARPS_M, int WARPS_N, int MIN_CTAS>
__global__ __launch_bounds__(WARPS_M * WARPS_N * 32, MIN_CTAS)
void gemm_mma_kernel(const __half* __restrict__ A,
                     const __half* __restrict__ B,
                     float* __restrict__ C,
                     __half* __restrict__ Aout,
                     int mode, int ldc)
{
    constexpr int THREADS = WARPS_M * WARPS_N * 32;
    constexpr int MT  = BM / WARPS_M / 16;   // A 16-row subtiles per warp
    constexpr int NT2 = BN / WARPS_N / 16;   // B 16-row ldsm tiles per warp
    constexpr int NJ  = NT2 * 2;             // n8 column groups per warp
    constexpr int A_BYTES = BM * 128;
    constexpr int B_BYTES = BN * 128;
    constexpr int STAGE_BYTES = A_BYTES + B_BYTES;
    constexpr int A_IT = BM * 8 / THREADS;
    constexpr int B_IT = BN * 8 / THREADS;

    extern __shared__ char smem_raw[];
    const uint32_t sbase = (smem_u32(smem_raw) + 1023u) & ~1023u;

    const int tid = threadIdx.x;
    const int wid = tid >> 5, lane = tid & 31;
    const int wm = wid / WARPS_N;
    const int wn = wid % WARPS_N;
    const size_t arow0 = (size_t)blockIdx.y * BM;
    const size_t brow0 = (size_t)blockIdx.x * BN;

    const int lr = lane & 15;
    const int lseg = (lane >> 4) * 16;

    float acc[MT][NJ][4];
#pragma unroll
    for (int mt = 0; mt < MT; mt++)
#pragma unroll
        for (int j = 0; j < NJ; j++)
#pragma unroll
            for (int e = 0; e < 4; e++) acc[mt][j][e] = 0.f;

    uint32_t af[2][MT][4], bf[2][NT2][4];

    const char* Abase = (const char*)(A + arow0 * KSPLIT);
    const char* Bbase = (const char*)(B + brow0 * KSPLIT);
    auto load_chunk = [&](int c, int s) {
        const uint32_t sA = sbase + s * STAGE_BYTES;
        const uint32_t sB = sA + A_BYTES;
        const size_t cb = (size_t)c * 128;
#pragma unroll
        for (int i = 0; i < A_IT; i++) {
            int p = tid + i * THREADS;
            int r = p >> 3, seg = (p & 7) * 16;
            CP_ASYNC16(sA + swz(r, seg), Abase + (size_t)r * (KSPLIT * 2) + cb + seg);
        }
#pragma unroll
        for (int i = 0; i < B_IT; i++) {
            int p = tid + i * THREADS;
            int r = p >> 3, seg = (p & 7) * 16;
            CP_ASYNC16(sB + swz(r, seg), Bbase + (size_t)r * (KSPLIT * 2) + cb + seg);
        }
        CP_COMMIT();
    };

    auto ldfrag = [&](int s, int kk, int buf) {
        const uint32_t sA = sbase + s * STAGE_BYTES;
        const uint32_t sB = sA + A_BYTES;
#pragma unroll
        for (int mt = 0; mt < MT; mt++)
            ldsm4(af[buf][mt], sA + swz(wm * (MT * 16) + mt * 16 + lr, kk * 32 + lseg));
#pragma unroll
        for (int nt = 0; nt < NT2; nt++)
            ldsm4(bf[buf][nt], sB + swz(wn * (NT2 * 16) + nt * 16 + lr, kk * 32 + lseg));
    };

    auto domma = [&](int buf) {
#pragma unroll
        for (int mt = 0; mt < MT; mt++)
#pragma unroll
            for (int nt = 0; nt < NT2; nt++)
#pragma unroll
                for (int h = 0; h < 2; h++)
                    mma16816(acc[mt][nt * 2 + h], af[buf][mt],
                             bf[buf][nt][h], bf[buf][nt][h + 2]);
    };

    load_chunk(0, 0);
    load_chunk(1, 1);

    for (int c = 0; c < NCHUNK; c++) {
        // Ensure chunk c complete (committed >=2 iterations ago).
        if (c + 1 < NCHUNK) { CP_WAIT(1); } else { CP_WAIT(0); }
        __syncthreads();   // visibility of chunk c; all warps done with stage (c+2)%3's old tenant
        if (c + 2 < NCHUNK) load_chunk(c + 2, (c + 2) % NSTAGE);
        const int s = c % NSTAGE;
        ldfrag(s, 0, 0);
#pragma unroll
        for (int kk = 0; kk < 4; kk++) {
            if (kk < 3) ldfrag(s, kk + 1, (kk + 1) & 1);   // overlap next ldsm with this mma
            domma(kk & 1);
        }
    }

    // Epilogue. C-frag mapping: lane l -> rows (l>>2, l>>2+8), cols 2*(l&3)+{0,1}.
    const int r0 = lane >> 2;
    const int cb2 = 2 * (lane & 3);
    if (mode == 0) {
#pragma unroll
        for (int mt = 0; mt < MT; mt++) {
#pragma unroll
            for (int j = 0; j < NJ; j++) {
                size_t row = arow0 + wm * (MT * 16) + mt * 16 + r0;
                size_t col = brow0 + wn * (NJ * 8) + j * 8 + cb2;
                *(float2*)(C + row * ldc + col)       = make_float2(acc[mt][j][0], acc[mt][j][1]);
                *(float2*)(C + (row + 8) * ldc + col) = make_float2(acc[mt][j][2], acc[mt][j][3]);
            }
        }
    } else {
#pragma unroll
        for (int mt = 0; mt < MT; mt++) {
#pragma unroll
            for (int j = 0; j < NJ; j++) {
                int col = (int)brow0 + wn * (NJ * 8) + j * 8 + cb2;   // < 1024
#pragma unroll
                for (int h = 0; h < 2; h++) {
                    size_t row = arow0 + wm * (MT * 16) + mt * 16 + r0 + h * 8;
                    __half* dr = Aout + row * KSPLIT;
                    __half2 hv;
                    hv.x = __float2half(acc[mt][j][2 * h]);
                    hv.y = __float2half(acc[mt][j][2 * h + 1]);
                    *(__half2*)(dr + col) = hv;
                }
            }
        }
    }
}

// ---------------------------------------------------------------------------
// Per-image Gram matrix
// ---------------------------------------------------------------------------
__global__ void gram_kernel(const float* __restrict__ images)
{
    __shared__ float T[SS][65];
    const int b = blockIdx.x;
    const int tid = threadIdx.x;
    float acc[6] = {0.f, 0.f, 0.f, 0.f, 0.f, 0.f};
    for (int d0 = 0; d0 < DD; d0 += 64) {
        __syncthreads();
        for (int i = tid; i < SS * 64; i += 256) {
            int r = i / 64, c = i % 64;
            T[r][c] = images[((size_t)b * SS + r) * DD + d0 + c];
        }
        __syncthreads();
#pragma unroll
        for (int pi = 0; pi < 6; pi++) {
            int p = tid + pi * 256;
            if (p < SS * SS) {
                int s = p / SS, s2 = p % SS;
                float sum = 0.f;
#pragma unroll
                for (int k = 0; k < 64; k++) sum += T[s][k] * T[s2][k];
                acc[pi] += sum;
            }
        }
    }
#pragma unroll
    for (int pi = 0; pi < 6; pi++) {
        int p = tid + pi * 256;
        if (p < SS * SS) g_G[b * SS * SS + p] = acc[pi];
    }
}

__global__ void w1_kernel(const float* __restrict__ captions)
{
    const int row = blockIdx.x * 8 + (threadIdx.x >> 5);
    const int lane = threadIdx.x & 31;
    const float* p = captions + (size_t)row * DD;
    float s = 0.f;
    for (int k = lane; k < DD; k += 32) { float v = p[k]; s += v * v; }
#pragma unroll
    for (int o = 16; o; o >>= 1) s += __shfl_xor_sync(0xffffffffu, s, o);
    if (lane == 0) g_w1[row] = sqrtf(s);
}

// ---------------------------------------------------------------------------
// Final epilogue: one block per (caption i, image b)
// ---------------------------------------------------------------------------
__global__ __launch_bounds__(128)
void epilogue_kernel(const int* __restrict__ cap_lens, float* __restrict__ out)
{
    const int i = blockIdx.x;
    const int b = blockIdx.y;

    __shared__ float sA[SS][LL];
    __shared__ float sC[SS][LL];
    __shared__ float sQ[SS][LL];
    __shared__ float sG[SS][SS];
    __shared__ float snorm[SS];

    const int tid = threadIdx.x;
    const int len = cap_lens[i];

    for (int p = tid; p < SS * SS; p += 128)
        sG[p / SS][p % SS] = g_G[b * SS * SS + p];

    for (int p = tid; p < SS * LL; p += 128) {
        int s = p / LL, l = p % LL;
        size_t col = (size_t)i * LL + l;
        float a = g_X[(size_t)(MROWS + b * SS + s) * XCOLS + col];  // attn logits (Y.cap)
        a = (a > 0.f) ? a : 0.1f * a;
        if (l >= len) a = 0.f;
        sA[s][l] = a;
        sC[s][l] = g_X[(size_t)(b * SS + s) * XCOLS + col];          // cap . img
    }
    __syncthreads();

    if (tid < SS) {
        float s2 = 0.f;
#pragma unroll
        for (int l = 0; l < LL; l++) { float v = sA[tid][l]; s2 += v * v; }
        snorm[tid] = 1.f / (sqrtf(s2) + EPSF);
    }
    __syncthreads();

    if (tid < LL) {
        const int l = tid;
        float vals[SS];
        float m = -CUDART_INF_F;
#pragma unroll
        for (int s = 0; s < SS; s++) {
            float v = sA[s][l] * snorm[s] * SMOOTHF;
            vals[s] = v;
            m = fmaxf(m, v);
        }
        float sum = 0.f;
#pragma unroll
        for (int s = 0; s < SS; s++) {
            float e = fexp(vals[s] - m);     // FMA-pipe exp (finite args only)
            vals[s] = e;
            sum += e;
        }
        float inv = 1.f / sum;
#pragma unroll
        for (int s = 0; s < SS; s++) sA[s][l] = vals[s] * inv;
    }
    __syncthreads();

    for (int p = tid; p < SS * LL; p += 128) {
        int s = p / LL, l = p % LL;
        float sum = 0.f;
#pragma unroll
        for (int s2 = 0; s2 < SS; s2++) sum += sG[s][s2] * sA[s2][l];
        sQ[s][l] = sum;
    }
    __syncthreads();

    if (tid < LL) {
        const int l = tid;
        float w12 = 0.f, w2q = 0.f;
#pragma unroll
        for (int s = 0; s < SS; s++) {
            float p = sA[s][l];
            w12 += p * sC[s][l];
            w2q += p * sQ[s][l];
        }
        float w2 = sqrtf(fmaxf(w2q, 0.f));
        float w1 = g_w1[i * LL + l];
        float r = w12 / fmaxf(w1 * w2, EPSF);

        float z = (l < len) ? r * LAMBDAF : -CUDART_INF_F;
        float m = z;
#pragma unroll
        for (int o = 16; o; o >>= 1) m = fmaxf(m, __shfl_xor_sync(0xffffffffu, m, o));
        float e = (l < len) ? fexp(z - m) : 0.f;   // guarded: finite args only
#pragma unroll
        for (int o = 16; o; o >>= 1) e += __shfl_xor_sync(0xffffffffu, e, o);
        if (l == 0) out[b * NB + i] = (logf(e) + m) / LAMBDAF;
    }
}

// ---------------------------------------------------------------------------
extern "C" void kernel_launch(void* const* d_in, const int* in_sizes, int n_in,
                              void* d_out, int out_size)
{
    const float* images   = (const float*)d_in[0];  // (64, 36, 1024)
    const float* captions = (const float*)d_in[1];  // (64, 32, 1024)
    const int*   cap_lens = (const int*)  d_in[2];  // (64,)
    const float* W_g      = (const float*)d_in[3];  // (1024, 1024)
    float* out = (float*)d_out;                     // (64, 64)

    __half *pA2, *pB2, *pBW;
    float *pX;
    cudaGetSymbolAddress((void**)&pA2, g_A2);
    cudaGetSymbolAddress((void**)&pB2, g_B2);
    cudaGetSymbolAddress((void**)&pBW, g_BW);
    cudaGetSymbolAddress((void**)&pX,  g_X);

    // P variant: BM=64, BN=64, warps 2x2 (128 thr), 4 CTAs/SM.  smem = 50176; grid (16,36)
    // X variant: BM=128, BN=256, warps 2x4 (256 thr), 64x64 warp tiles, 1 CTA/SM.
    //            smem = 148480; grid (8,36)
    const int SMEM_P = NSTAGE * (64 + 64) * 128 + 1024;
    const int SMEM_X = NSTAGE * (128 + 256) * 128 + 1024;
    cudaFuncSetAttribute((const void*)gemm_mma_kernel<64, 64, 2, 2, 4>,
                         cudaFuncAttributeMaxDynamicSharedMemorySize, SMEM_P);
    cudaFuncSetAttribute((const void*)gemm_mma_kernel<128, 256, 2, 4, 1>,
                         cudaFuncAttributeMaxDynamicSharedMemorySize, SMEM_X);

    // 1) fp32 -> fp16 converts (single launch for images+captions) + W transpose
    cvt_both_kernel<<<(MROWS + CROWS) * DD / 512, 256>>>(images, captions, pA2, pB2);
    {
        dim3 grid(DD / 32, DD / 32);
        cvt_w_kernel<<<grid, dim3(32, 32)>>>(W_g);
    }

    // 2) GEMM-P: Y = images_h @ W_h -> fp16 into g_A2 rows [2304, 4608)
    {
        dim3 grid(DD / 64, MROWS / 64);
        gemm_mma_kernel<64, 64, 2, 2, 4><<<grid, 128, SMEM_P>>>(pA2, pBW, nullptr,
                                                                pA2 + (size_t)MROWS * KSPLIT, 1, 0);
    }
    // 3) GEMM-X: X = [images_h ; Y_h] @ captions_h^T  (4608 x 2048, fp32)
    {
        dim3 grid(XCOLS / 256, AROWS / 128);
        gemm_mma_kernel<128, 256, 2, 4, 1><<<grid, 256, SMEM_X>>>(pA2, pB2, pX, nullptr, 0, XCOLS);
    }

    // 4) Gram + caption norms (fp32 inputs, exact)
    gram_kernel<<<NB, 256>>>(images);
    w1_kernel<<<CROWS / 8, 256>>>(captions);

    // 5) Final epilogue
    {
        dim3 grid(NB, NB);
        epilogue_kernel<<<grid, 128>>>(cap_lens, out);
    }
}

// round 13
// speedup vs baseline: 2.4136x; 1.8000x over previous
#include <cuda_runtime.h>
#include <cuda_fp16.h>
#include <math_constants.h>
#include <cstdint>

// Problem constants
#define DD     1024
#define NB     64
#define SS     36
#define LL     32
#define SMOOTHF 9.0f
#define LAMBDAF 6.0f
#define EPSF   1e-8f

#define MROWS  (NB*SS)       // 2304 image rows
#define CROWS  (NB*LL)       // 2048 caption rows
#define AROWS  (2*MROWS)     // 4608 = [images ; Y]
#define KSPLIT 1024          // plain fp16
#define XCOLS  CROWS         // 2048

#define BK 64                        // fp16 elems per chunk = 128 B rows
#define NCHUNK (KSPLIT / BK)         // 16

// Scratch (static device globals; allocation forbidden)
__device__ __half g_A2[(size_t)AROWS * KSPLIT];  // [images_h ; Y_h]
__device__ __half g_B2[(size_t)CROWS * KSPLIT];  // captions_h
__device__ __half g_BW[(size_t)DD   * KSPLIT];   // W_g^T fp16
__device__ float g_X[(size_t)AROWS * XCOLS];     // fused GEMM output fp32
__device__ float g_Gf[NB * 64 * 64];             // padded per-image Gram (64x64 tiles)
__device__ float g_w1[CROWS];

// ---------------------------------------------------------------------------
// PTX helpers (base-ISA only: cp.async, ldmatrix, mma.sync)
// ---------------------------------------------------------------------------
__device__ __forceinline__ uint32_t smem_u32(const void* p) {
    uint32_t a;
    asm("{ .reg .u64 t; cvta.to.shared.u64 t, %1; cvt.u32.u64 %0, t; }" : "=r"(a) : "l"(p));
    return a;
}
#define CP_ASYNC16(dst, src) \
    asm volatile("cp.async.cg.shared.global [%0], [%1], 16;\n" :: "r"(dst), "l"(src))
#define CP_COMMIT() asm volatile("cp.async.commit_group;\n" ::: "memory")
#define CP_WAIT(n)  asm volatile("cp.async.wait_group %0;\n" :: "n"(n) : "memory")

__device__ __forceinline__ void ldsm4(uint32_t* r, uint32_t addr) {
    asm volatile("ldmatrix.sync.aligned.m8n8.x4.shared.b16 {%0,%1,%2,%3}, [%4];"
                 : "=r"(r[0]), "=r"(r[1]), "=r"(r[2]), "=r"(r[3]) : "r"(addr));
}
__device__ __forceinline__ void mma16816(float* c, const uint32_t* a,
                                         uint32_t b0, uint32_t b1) {
    asm volatile("mma.sync.aligned.m16n8k16.row.col.f32.f16.f16.f32 "
                 "{%0,%1,%2,%3}, {%4,%5,%6,%7}, {%8,%9}, {%0,%1,%2,%3};"
                 : "+f"(c[0]), "+f"(c[1]), "+f"(c[2]), "+f"(c[3])
                 : "r"(a[0]), "r"(a[1]), "r"(a[2]), "r"(a[3]), "r"(b0), "r"(b1));
}
// SW128 swizzle for 128B rows
__device__ __forceinline__ uint32_t swz(int row, int seg) {
    return (uint32_t)(row * 128 + (seg ^ ((row & 7) << 4)));
}

// Fast exp on the FMA pipe (no MUFU). Valid for finite x in (-87, 20).
__device__ __forceinline__ float fexp(float x) {
    const float L2E = 1.4426950408889634f;
    float t = fmaf(x, L2E, 12582912.0f);
    float i = t - 12582912.0f;
    float f = fmaf(x, L2E, -i);
    float p = 1.3333558146e-3f;
    p = fmaf(p, f, 9.6181291076e-3f);
    p = fmaf(p, f, 5.5504108665e-2f);
    p = fmaf(p, f, 2.4022650696e-1f);
    p = fmaf(p, f, 6.9314718056e-1f);
    p = fmaf(p, f, 1.0f);
    return __int_as_float(__float_as_int(p) + (((int)i) << 23));
}

// ---------------------------------------------------------------------------
// fp32 -> fp16 converts (single fused launch) + W transpose
// ---------------------------------------------------------------------------
#define IMG_PAIRS (MROWS * DD / 2)
__global__ void cvt_both_kernel(const float* __restrict__ images,
                                const float* __restrict__ captions,
                                __half* __restrict__ dimg, __half* __restrict__ dcap)
{
    int i = blockIdx.x * 256 + threadIdx.x;
    const float* src; __half* dst; int j;
    if (i < IMG_PAIRS) { src = images;   dst = dimg; j = i; }
    else               { src = captions; dst = dcap; j = i - IMG_PAIRS; }
    float2 v = *(const float2*)(src + 2 * j);
    __half2 h; h.x = __float2half(v.x); h.y = __float2half(v.y);
    *(__half2*)(dst + 2 * j) = h;
}

__global__ void cvt_w_kernel(const float* __restrict__ W)
{
    __shared__ float t[32][33];
    int k0 = blockIdx.y * 32, n0 = blockIdx.x * 32;
    int tx = threadIdx.x, ty = threadIdx.y;
    t[ty][tx] = W[(size_t)(k0 + ty) * DD + n0 + tx];
    __syncthreads();
    g_BW[(size_t)(n0 + ty) * KSPLIT + k0 + tx] = __float2half(t[tx][ty]);
}

// ---------------------------------------------------------------------------
// HMMA NT GEMM: C[m,n] = sum_k A[m,k]*B[n,k], K = KSPLIT.
// Load row bases: A rows start at by*arowmul; B rows at bx*BN + by*browadd.
// Store bases: C row = by*BM, C col = bx*BN.   (arowmul=BM, browadd=0 => classic)
// STAGES-deep cp.async pipeline; register double-buffered ldmatrix fragments.
// mode 0: write fp32 C (ldc). mode 1: write fp16 rows into Aout.
// ---------------------------------------------------------------------------
template<int BM, int BN, int WARPS_M, int WARPS_N, int STAGES, int MIN_CTAS>
__global__ __launch_bounds__(WARPS_M * WARPS_N * 32, MIN_CTAS)
void gemm_mma_kernel(const __half* __restrict__ A,
                     const __half* __restrict__ B,
                     float* __restrict__ C,
                     __half* __restrict__ Aout,
                     int mode, int ldc, int arowmul, int browadd)
{
    constexpr int THREADS = WARPS_M * WARPS_N * 32;
    constexpr int MT  = BM / WARPS_M / 16;
    constexpr int NT2 = BN / WARPS_N / 16;
    constexpr int NJ  = NT2 * 2;
    constexpr int A_BYTES = BM * 128;
    constexpr int B_BYTES = BN * 128;
    constexpr int STAGE_BYTES = A_BYTES + B_BYTES;
    constexpr int A_IT = BM * 8 / THREADS;
    constexpr int B_IT = BN * 8 / THREADS;

    extern __shared__ char smem_raw[];
    const uint32_t sbase = (smem_u32(smem_raw) + 1023u) & ~1023u;

    const int tid = threadIdx.x;
    const int wid = tid >> 5, lane = tid & 31;
    const int wm = wid / WARPS_N;
    const int wn = wid % WARPS_N;
    const size_t arow0 = (size_t)blockIdx.y * arowmul;
    const size_t brow0 = (size_t)blockIdx.x * BN + (size_t)blockIdx.y * browadd;

    const int lr = lane & 15;
    const int lseg = (lane >> 4) * 16;

    float acc[MT][NJ][4];
#pragma unroll
    for (int mt = 0; mt < MT; mt++)
#pragma unroll
        for (int j = 0; j < NJ; j++)
#pragma unroll
            for (int e = 0; e < 4; e++) acc[mt][j][e] = 0.f;

    uint32_t af[2][MT][4], bf[2][NT2][4];

    const char* Abase = (const char*)(A + arow0 * KSPLIT);
    const char* Bbase = (const char*)(B + brow0 * KSPLIT);
    auto load_chunk = [&](int c, int s) {
        const uint32_t sA = sbase + s * STAGE_BYTES;
        const uint32_t sB = sA + A_BYTES;
        const size_t cb = (size_t)c * 128;
#pragma unroll
        for (int i = 0; i < A_IT; i++) {
            int p = tid + i * THREADS;
            int r = p >> 3, seg = (p & 7) * 16;
            CP_ASYNC16(sA + swz(r, seg), Abase + (size_t)r * (KSPLIT * 2) + cb + seg);
        }
#pragma unroll
        for (int i = 0; i < B_IT; i++) {
            int p = tid + i * THREADS;
            int r = p >> 3, seg = (p & 7) * 16;
            CP_ASYNC16(sB + swz(r, seg), Bbase + (size_t)r * (KSPLIT * 2) + cb + seg);
        }
        CP_COMMIT();
    };

    auto ldfrag = [&](int s, int kk, int buf) {
        const uint32_t sA = sbase + s * STAGE_BYTES;
        const uint32_t sB = sA + A_BYTES;
#pragma unroll
        for (int mt = 0; mt < MT; mt++)
            ldsm4(af[buf][mt], sA + swz(wm * (MT * 16) + mt * 16 + lr, kk * 32 + lseg));
#pragma unroll
        for (int nt = 0; nt < NT2; nt++)
            ldsm4(bf[buf][nt], sB + swz(wn * (NT2 * 16) + nt * 16 + lr, kk * 32 + lseg));
    };

    auto domma = [&](int buf) {
#pragma unroll
        for (int mt = 0; mt < MT; mt++)
#pragma unroll
            for (int nt = 0; nt < NT2; nt++)
#pragma unroll
                for (int h = 0; h < 2; h++)
                    mma16816(acc[mt][nt * 2 + h], af[buf][mt],
                             bf[buf][nt][h], bf[buf][nt][h + 2]);
    };

#pragma unroll
    for (int s = 0; s < STAGES - 1; s++) load_chunk(s, s);

    for (int c = 0; c < NCHUNK; c++) {
        // Ensure chunk c complete.
        if (c + STAGES - 2 < NCHUNK)      { CP_WAIT(STAGES - 2); }
        else if (c + 2 < NCHUNK)          { CP_WAIT(2); }
        else if (c + 1 < NCHUNK)          { CP_WAIT(1); }
        else                              { CP_WAIT(0); }
        __syncthreads();   // all warps past compute of chunk c-1; chunk c visible
        if (c + STAGES - 1 < NCHUNK) load_chunk(c + STAGES - 1, (c + STAGES - 1) % STAGES);
        const int s = c % STAGES;
        ldfrag(s, 0, 0);
#pragma unroll
        for (int kk = 0; kk < 4; kk++) {
            if (kk < 3) ldfrag(s, kk + 1, (kk + 1) & 1);
            domma(kk & 1);
        }
    }

    // Epilogue. C-frag mapping: lane l -> rows (l>>2, l>>2+8), cols 2*(l&3)+{0,1}.
    const size_t crow0 = (size_t)blockIdx.y * BM;
    const int ccol0 = blockIdx.x * BN;
    const int r0 = lane >> 2;
    const int cb2 = 2 * (lane & 3);
    if (mode == 0) {
#pragma unroll
        for (int mt = 0; mt < MT; mt++) {
#pragma unroll
            for (int j = 0; j < NJ; j++) {
                size_t row = crow0 + wm * (MT * 16) + mt * 16 + r0;
                size_t col = ccol0 + wn * (NJ * 8) + j * 8 + cb2;
                *(float2*)(C + row * ldc + col)       = make_float2(acc[mt][j][0], acc[mt][j][1]);
                *(float2*)(C + (row + 8) * ldc + col) = make_float2(acc[mt][j][2], acc[mt][j][3]);
            }
        }
    } else {
#pragma unroll
        for (int mt = 0; mt < MT; mt++) {
#pragma unroll
            for (int j = 0; j < NJ; j++) {
                int col = ccol0 + wn * (NJ * 8) + j * 8 + cb2;   // < 1024
#pragma unroll
                for (int h = 0; h < 2; h++) {
                    size_t row = crow0 + wm * (MT * 16) + mt * 16 + r0 + h * 8;
                    __half* dr = Aout + row * KSPLIT;
                    __half2 hv;
                    hv.x = __float2half(acc[mt][j][2 * h]);
                    hv.y = __float2half(acc[mt][j][2 * h + 1]);
                    *(__half2*)(dr + col) = hv;
                }
            }
        }
    }
}

// ---------------------------------------------------------------------------
// Caption word norms
// ---------------------------------------------------------------------------
__global__ void w1_kernel(const float* __restrict__ captions)
{
    const int row = blockIdx.x * 8 + (threadIdx.x >> 5);
    const int lane = threadIdx.x & 31;
    const float* p = captions + (size_t)row * DD;
    float s = 0.f;
    for (int k = lane; k < DD; k += 32) { float v = p[k]; s += v * v; }
#pragma unroll
    for (int o = 16; o; o >>= 1) s += __shfl_xor_sync(0xffffffffu, s, o);
    if (lane == 0) g_w1[row] = sqrtf(s);
}

// ---------------------------------------------------------------------------
// Final epilogue: one block per (caption i, image b); one heavy warp per block
// (rotated across SMSPs) does softmax + p^T G p with register-resident probs.
// ---------------------------------------------------------------------------
__global__ __launch_bounds__(128)
void epilogue_kernel(const int* __restrict__ cap_lens, float* __restrict__ out)
{
    const int i = blockIdx.x;
    const int b = blockIdx.y;

    __shared__ float sA[SS][LL + 1];   // attn (leaky+masked); pad kills bank conflicts
    __shared__ float sC[SS][LL + 1];   // cap . img
    __shared__ float sG[SS][SS];       // Gram (broadcast access only)
    __shared__ float snorm[SS];

    const int tid = threadIdx.x;
    const int len = cap_lens[i];

    // Stage attn + capdot (coalesced) and Gram rows
#pragma unroll
    for (int it = 0; it < 9; it++) {
        int p = tid + it * 128;
        int s = p >> 5, l = p & 31;
        size_t col = (size_t)i * LL + l;
        float a = g_X[(size_t)(MROWS + b * SS + s) * XCOLS + col];
        a = (a > 0.f) ? a : 0.1f * a;
        if (l >= len) a = 0.f;
        sA[s][l] = a;
        sC[s][l] = g_X[(size_t)(b * SS + s) * XCOLS + col];
    }
    for (int p = tid; p < SS * SS; p += 128)
        sG[p / SS][p % SS] = g_Gf[(b * 64 + p / SS) * 64 + p % SS];
    __syncthreads();

    if (tid < SS) {
        float s2 = 0.f;
#pragma unroll
        for (int l = 0; l < LL; l++) { float v = sA[tid][l]; s2 += v * v; }
        snorm[tid] = 1.f / (sqrtf(s2) + EPSF);
    }
    __syncthreads();

    // Heavy warp (rotates across SMSPs with blockIdx.x)
    if ((tid >> 5) == (i & 3)) {
        const int l = tid & 31;
        float vals[SS];
#pragma unroll
        for (int s = 0; s < SS; s++) vals[s] = sA[s][l] * snorm[s] * SMOOTHF;

        float m = vals[0];
#pragma unroll
        for (int s = 1; s < SS; s++) m = fmaxf(m, vals[s]);
        float sum = 0.f;
#pragma unroll
        for (int s = 0; s < SS; s++) { float e = fexp(vals[s] - m); vals[s] = e; sum += e; }
        float inv = 1.f / sum;
#pragma unroll
        for (int s = 0; s < SS; s++) vals[s] *= inv;

        float w12 = 0.f, w2q = 0.f;
#pragma unroll
        for (int s = 0; s < SS; s++) {
            float inner = 0.f;
#pragma unroll
            for (int s2 = 0; s2 < SS; s2++) inner = fmaf(sG[s][s2], vals[s2], inner);
            w2q = fmaf(vals[s], inner, w2q);
            w12 = fmaf(vals[s], sC[s][l], w12);
        }
        float w2 = sqrtf(fmaxf(w2q, 0.f));
        float w1 = g_w1[i * LL + l];
        float r = w12 / fmaxf(w1 * w2, EPSF);

        float z = (l < len) ? r * LAMBDAF : -1e30f;
        float mm = z;
#pragma unroll
        for (int o = 16; o; o >>= 1) mm = fmaxf(mm, __shfl_xor_sync(0xffffffffu, mm, o));
        float e = (l < len) ? fexp(z - mm) : 0.f;
#pragma unroll
        for (int o = 16; o; o >>= 1) e += __shfl_xor_sync(0xffffffffu, e, o);
        if (l == 0) out[b * NB + i] = (logf(e) + mm) / LAMBDAF;
    }
}

// ---------------------------------------------------------------------------
extern "C" void kernel_launch(void* const* d_in, const int* in_sizes, int n_in,
                              void* d_out, int out_size)
{
    const float* images   = (const float*)d_in[0];  // (64, 36, 1024)
    const float* captions = (const float*)d_in[1];  // (64, 32, 1024)
    const int*   cap_lens = (const int*)  d_in[2];  // (64,)
    const float* W_g      = (const float*)d_in[3];  // (1024, 1024)
    float* out = (float*)d_out;                     // (64, 64)

    __half *pA2, *pB2, *pBW;
    float *pX, *pGf;
    cudaGetSymbolAddress((void**)&pA2, g_A2);
    cudaGetSymbolAddress((void**)&pB2, g_B2);
    cudaGetSymbolAddress((void**)&pBW, g_BW);
    cudaGetSymbolAddress((void**)&pX,  g_X);
    cudaGetSymbolAddress((void**)&pGf, g_Gf);

    // P/gram variant: BM=64, BN=64, warps 2x2, 3 stages, 4 CTAs/SM. smem = 50176
    // X variant:      BM=128, BN=256, warps 2x4, 4 stages, 1 CTA/SM. smem = 197632
    const int SMEM_P = 3 * (64 + 64) * 128 + 1024;
    const int SMEM_X = 4 * (128 + 256) * 128 + 1024;
    cudaFuncSetAttribute((const void*)gemm_mma_kernel<64, 64, 2, 2, 3, 4>,
                         cudaFuncAttributeMaxDynamicSharedMemorySize, SMEM_P);
    cudaFuncSetAttribute((const void*)gemm_mma_kernel<128, 256, 2, 4, 4, 1>,
                         cudaFuncAttributeMaxDynamicSharedMemorySize, SMEM_X);

    // 1) fp32 -> fp16 converts + W transpose
    cvt_both_kernel<<<(MROWS + CROWS) * DD / 512, 256>>>(images, captions, pA2, pB2);
    {
        dim3 grid(DD / 32, DD / 32);
        cvt_w_kernel<<<grid, dim3(32, 32)>>>(W_g);
    }

    // 2) GEMM-P: Y = images_h @ W_h -> fp16 into g_A2 rows [2304, 4608)
    {
        dim3 grid(DD / 64, MROWS / 64);
        gemm_mma_kernel<64, 64, 2, 2, 3, 4><<<grid, 128, SMEM_P>>>(
            pA2, pBW, nullptr, pA2 + (size_t)MROWS * KSPLIT, 1, 0, 64, 0);
    }
    // 3) Gram via tensor cores: G_b = img_h[b] @ img_h[b]^T (padded 64x64 tiles)
    //    grid (1, 64): A/B rows start at b*36; C tile at rows b*64, cols 0..63.
    {
        dim3 grid(1, NB);
        gemm_mma_kernel<64, 64, 2, 2, 3, 4><<<grid, 128, SMEM_P>>>(
            pA2, pA2, pGf, nullptr, 0, 64, SS, SS);
    }
    // 4) GEMM-X: X = [images_h ; Y_h] @ captions_h^T  (4608 x 2048, fp32)
    {
        dim3 grid(XCOLS / 256, AROWS / 128);
        gemm_mma_kernel<128, 256, 2, 4, 4, 1><<<grid, 256, SMEM_X>>>(
            pA2, pB2, pX, nullptr, 0, XCOLS, 128, 0);
    }

    // 5) Caption norms (fp32, exact)
    w1_kernel<<<CROWS / 8, 256>>>(captions);

    // 6) Final epilogue
    {
        dim3 grid(NB, NB);
        epilogue_kernel<<<grid, 128>>>(cap_lens, out);
    }
}

// round 14
// speedup vs baseline: 2.4254x; 1.0049x over previous
#include <cuda_runtime.h>
#include <cuda_fp16.h>
#include <math_constants.h>
#include <cstdint>

// Problem constants
#define DD     1024
#define NB     64
#define SS     36
#define LL     32
#define SMOOTHF 9.0f
#define LAMBDAF 6.0f
#define EPSF   1e-8f

#define MROWS  (NB*SS)       // 2304 image rows
#define CROWS  (NB*LL)       // 2048 caption rows
#define AROWS  (2*MROWS)     // 4608 = [images ; Y]
#define KSPLIT 1024          // plain fp16
#define XCOLS  CROWS         // 2048

#define BK 64                        // fp16 elems per chunk = 128 B rows
#define NCHUNK (KSPLIT / BK)         // 16
#define GSLABS 4                     // split-K factor for Gram
#define GSTRIDE ((size_t)NB * 64 * 64)

// Scratch (static device globals; allocation forbidden)
__device__ __half g_A2[(size_t)AROWS * KSPLIT];  // [images_h ; Y_h]
__device__ __half g_B2[(size_t)CROWS * KSPLIT];  // captions_h
__device__ __half g_BW[(size_t)DD   * KSPLIT];   // W_g^T fp16
__device__ float g_X[(size_t)AROWS * XCOLS];     // fused GEMM output fp32
__device__ float g_Gf[GSLABS * NB * 64 * 64];    // split-K partial Grams (16MB)
__device__ float g_w1[CROWS];

// ---------------------------------------------------------------------------
// PTX helpers (base-ISA only: cp.async, ldmatrix, mma.sync)
// ---------------------------------------------------------------------------
__device__ __forceinline__ uint32_t smem_u32(const void* p) {
    uint32_t a;
    asm("{ .reg .u64 t; cvta.to.shared.u64 t, %1; cvt.u32.u64 %0, t; }" : "=r"(a) : "l"(p));
    return a;
}
#define CP_ASYNC16(dst, src) \
    asm volatile("cp.async.cg.shared.global [%0], [%1], 16;\n" :: "r"(dst), "l"(src))
#define CP_COMMIT() asm volatile("cp.async.commit_group;\n" ::: "memory")
#define CP_WAIT(n)  asm volatile("cp.async.wait_group %0;\n" :: "n"(n) : "memory")

__device__ __forceinline__ void ldsm4(uint32_t* r, uint32_t addr) {
    asm volatile("ldmatrix.sync.aligned.m8n8.x4.shared.b16 {%0,%1,%2,%3}, [%4];"
                 : "=r"(r[0]), "=r"(r[1]), "=r"(r[2]), "=r"(r[3]) : "r"(addr));
}
__device__ __forceinline__ void mma16816(float* c, const uint32_t* a,
                                         uint32_t b0, uint32_t b1) {
    asm volatile("mma.sync.aligned.m16n8k16.row.col.f32.f16.f16.f32 "
                 "{%0,%1,%2,%3}, {%4,%5,%6,%7}, {%8,%9}, {%0,%1,%2,%3};"
                 : "+f"(c[0]), "+f"(c[1]), "+f"(c[2]), "+f"(c[3])
                 : "r"(a[0]), "r"(a[1]), "r"(a[2]), "r"(a[3]), "r"(b0), "r"(b1));
}
// SW128 swizzle for 128B rows
__device__ __forceinline__ uint32_t swz(int row, int seg) {
    return (uint32_t)(row * 128 + (seg ^ ((row & 7) << 4)));
}

// Fast exp on the FMA pipe (no MUFU). Valid for finite x in (-87, 20).
__device__ __forceinline__ float fexp(float x) {
    const float L2E = 1.4426950408889634f;
    float t = fmaf(x, L2E, 12582912.0f);
    float i = t - 12582912.0f;
    float f = fmaf(x, L2E, -i);
    float p = 1.3333558146e-3f;
    p = fmaf(p, f, 9.6181291076e-3f);
    p = fmaf(p, f, 5.5504108665e-2f);
    p = fmaf(p, f, 2.4022650696e-1f);
    p = fmaf(p, f, 6.9314718056e-1f);
    p = fmaf(p, f, 1.0f);
    return __int_as_float(__float_as_int(p) + (((int)i) << 23));
}

// ---------------------------------------------------------------------------
// fp32 -> fp16 converts (single fused launch) + W transpose
// ---------------------------------------------------------------------------
#define IMG_PAIRS (MROWS * DD / 2)
__global__ void cvt_both_kernel(const float* __restrict__ images,
                                const float* __restrict__ captions,
                                __half* __restrict__ dimg, __half* __restrict__ dcap)
{
    int i = blockIdx.x * 256 + threadIdx.x;
    const float* src; __half* dst; int j;
    if (i < IMG_PAIRS) { src = images;   dst = dimg; j = i; }
    else               { src = captions; dst = dcap; j = i - IMG_PAIRS; }
    float2 v = *(const float2*)(src + 2 * j);
    __half2 h; h.x = __float2half(v.x); h.y = __float2half(v.y);
    *(__half2*)(dst + 2 * j) = h;
}

__global__ void cvt_w_kernel(const float* __restrict__ W)
{
    __shared__ float t[32][33];
    int k0 = blockIdx.y * 32, n0 = blockIdx.x * 32;
    int tx = threadIdx.x, ty = threadIdx.y;
    t[ty][tx] = W[(size_t)(k0 + ty) * DD + n0 + tx];
    __syncthreads();
    g_BW[(size_t)(n0 + ty) * KSPLIT + k0 + tx] = __float2half(t[tx][ty]);
}

// ---------------------------------------------------------------------------
// HMMA NT GEMM: C[m,n] = sum_{k in chunk window} A[m,k]*B[n,k].
// Load row bases: A rows at by*arowmul; B rows at bx*BN + by*browadd.
// K window: chunks [bz*nch, (bz+1)*nch); partial C slab at C + bz*zstride.
// Store bases: C row = by*BM, col = bx*BN.
// STAGES-deep cp.async pipeline; register double-buffered ldmatrix fragments.
// mode 0: write fp32 C (ldc). mode 1: write fp16 rows into Aout.
// ---------------------------------------------------------------------------
template<int BM, int BN, int WARPS_M, int WARPS_N, int STAGES, int MIN_CTAS>
__global__ __launch_bounds__(WARPS_M * WARPS_N * 32, MIN_CTAS)
void gemm_mma_kernel(const __half* __restrict__ A,
                     const __half* __restrict__ B,
                     float* __restrict__ C,
                     __half* __restrict__ Aout,
                     int mode, int ldc, int arowmul, int browadd,
                     int nch, size_t zstride)
{
    constexpr int THREADS = WARPS_M * WARPS_N * 32;
    constexpr int MT  = BM / WARPS_M / 16;
    constexpr int NT2 = BN / WARPS_N / 16;
    constexpr int NJ  = NT2 * 2;
    constexpr int A_BYTES = BM * 128;
    constexpr int B_BYTES = BN * 128;
    constexpr int STAGE_BYTES = A_BYTES + B_BYTES;
    constexpr int A_IT = BM * 8 / THREADS;
    constexpr int B_IT = BN * 8 / THREADS;

    extern __shared__ char smem_raw[];
    const uint32_t sbase = (smem_u32(smem_raw) + 1023u) & ~1023u;

    const int tid = threadIdx.x;
    const int wid = tid >> 5, lane = tid & 31;
    const int wm = wid / WARPS_N;
    const int wn = wid % WARPS_N;
    const size_t arow0 = (size_t)blockIdx.y * arowmul;
    const size_t brow0 = (size_t)blockIdx.x * BN + (size_t)blockIdx.y * browadd;
    const int kbase = blockIdx.z * nch;          // chunk offset
    float* Cz = C + (size_t)blockIdx.z * zstride;

    const int lr = lane & 15;
    const int lseg = (lane >> 4) * 16;

    float acc[MT][NJ][4];
#pragma unroll
    for (int mt = 0; mt < MT; mt++)
#pragma unroll
        for (int j = 0; j < NJ; j++)
#pragma unroll
            for (int e = 0; e < 4; e++) acc[mt][j][e] = 0.f;

    uint32_t af[2][MT][4], bf[2][NT2][4];

    const char* Abase = (const char*)(A + arow0 * KSPLIT + (size_t)kbase * BK);
    const char* Bbase = (const char*)(B + brow0 * KSPLIT + (size_t)kbase * BK);
    auto load_chunk = [&](int c, int s) {
        const uint32_t sA = sbase + s * STAGE_BYTES;
        const uint32_t sB = sA + A_BYTES;
        const size_t cb = (size_t)c * 128;
#pragma unroll
        for (int i = 0; i < A_IT; i++) {
            int p = tid + i * THREADS;
            int r = p >> 3, seg = (p & 7) * 16;
            CP_ASYNC16(sA + swz(r, seg), Abase + (size_t)r * (KSPLIT * 2) + cb + seg);
        }
#pragma unroll
        for (int i = 0; i < B_IT; i++) {
            int p = tid + i * THREADS;
            int r = p >> 3, seg = (p & 7) * 16;
            CP_ASYNC16(sB + swz(r, seg), Bbase + (size_t)r * (KSPLIT * 2) + cb + seg);
        }
        CP_COMMIT();
    };

    auto ldfrag = [&](int s, int kk, int buf) {
        const uint32_t sA = sbase + s * STAGE_BYTES;
        const uint32_t sB = sA + A_BYTES;
#pragma unroll
        for (int mt = 0; mt < MT; mt++)
            ldsm4(af[buf][mt], sA + swz(wm * (MT * 16) + mt * 16 + lr, kk * 32 + lseg));
#pragma unroll
        for (int nt = 0; nt < NT2; nt++)
            ldsm4(bf[buf][nt], sB + swz(wn * (NT2 * 16) + nt * 16 + lr, kk * 32 + lseg));
    };

    auto domma = [&](int buf) {
#pragma unroll
        for (int mt = 0; mt < MT; mt++)
#pragma unroll
            for (int nt = 0; nt < NT2; nt++)
#pragma unroll
                for (int h = 0; h < 2; h++)
                    mma16816(acc[mt][nt * 2 + h], af[buf][mt],
                             bf[buf][nt][h], bf[buf][nt][h + 2]);
    };

#pragma unroll
    for (int s = 0; s < STAGES - 1; s++)
        if (s < nch) load_chunk(s, s);

    for (int c = 0; c < nch; c++) {
        // Ensure chunk c complete.
        if (c + STAGES - 2 < nch)      { CP_WAIT(STAGES - 2); }
        else if (c + 1 < nch)          { CP_WAIT(1); }
        else                           { CP_WAIT(0); }
        __syncthreads();   // all warps past compute of stage's old tenant; chunk c visible
        if (c + STAGES - 1 < nch) load_chunk(c + STAGES - 1, (c + STAGES - 1) % STAGES);
        const int s = c % STAGES;
        ldfrag(s, 0, 0);
#pragma unroll
        for (int kk = 0; kk < 4; kk++) {
            if (kk < 3) ldfrag(s, kk + 1, (kk + 1) & 1);
            domma(kk & 1);
        }
    }

    // Epilogue. C-frag mapping: lane l -> rows (l>>2, l>>2+8), cols 2*(l&3)+{0,1}.
    const size_t crow0 = (size_t)blockIdx.y * BM;
    const int ccol0 = blockIdx.x * BN;
    const int r0 = lane >> 2;
    const int cb2 = 2 * (lane & 3);
    if (mode == 0) {
#pragma unroll
        for (int mt = 0; mt < MT; mt++) {
#pragma unroll
            for (int j = 0; j < NJ; j++) {
                size_t row = crow0 + wm * (MT * 16) + mt * 16 + r0;
                size_t col = ccol0 + wn * (NJ * 8) + j * 8 + cb2;
                *(float2*)(Cz + row * ldc + col)       = make_float2(acc[mt][j][0], acc[mt][j][1]);
                *(float2*)(Cz + (row + 8) * ldc + col) = make_float2(acc[mt][j][2], acc[mt][j][3]);
            }
        }
    } else {
#pragma unroll
        for (int mt = 0; mt < MT; mt++) {
#pragma unroll
            for (int j = 0; j < NJ; j++) {
                int col = ccol0 + wn * (NJ * 8) + j * 8 + cb2;   // < 1024
#pragma unroll
                for (int h = 0; h < 2; h++) {
                    size_t row = crow0 + wm * (MT * 16) + mt * 16 + r0 + h * 8;
                    __half* dr = Aout + row * KSPLIT;
                    __half2 hv;
                    hv.x = __float2half(acc[mt][j][2 * h]);
                    hv.y = __float2half(acc[mt][j][2 * h + 1]);
                    *(__half2*)(dr + col) = hv;
                }
            }
        }
    }
}

// ---------------------------------------------------------------------------
// Caption word norms
// ---------------------------------------------------------------------------
__global__ void w1_kernel(const float* __restrict__ captions)
{
    const int row = blockIdx.x * 8 + (threadIdx.x >> 5);
    const int lane = threadIdx.x & 31;
    const float* p = captions + (size_t)row * DD;
    float s = 0.f;
    for (int k = lane; k < DD; k += 32) { float v = p[k]; s += v * v; }
#pragma unroll
    for (int o = 16; o; o >>= 1) s += __shfl_xor_sync(0xffffffffu, s, o);
    if (lane == 0) g_w1[row] = sqrtf(s);
}

// ---------------------------------------------------------------------------
// Final epilogue: one block per (caption i, image b); one heavy warp per block
// (rotated across SMSPs) does softmax + p^T G p with register-resident probs.
// ---------------------------------------------------------------------------
__global__ __launch_bounds__(128)
void epilogue_kernel(const int* __restrict__ cap_lens, float* __restrict__ out)
{
    const int i = blockIdx.x;
    const int b = blockIdx.y;

    __shared__ float sA[SS][LL + 1];   // attn (leaky+masked)
    __shared__ float sC[SS][LL + 1];   // cap . img
    __shared__ float sG[SS][SS];       // Gram (sum of split-K partials)
    __shared__ float snorm[SS];

    const int tid = threadIdx.x;
    const int len = cap_lens[i];

#pragma unroll
    for (int it = 0; it < 9; it++) {
        int p = tid + it * 128;
        int s = p >> 5, l = p & 31;
        size_t col = (size_t)i * LL + l;
        float a = g_X[(size_t)(MROWS + b * SS + s) * XCOLS + col];
        a = (a > 0.f) ? a : 0.1f * a;
        if (l >= len) a = 0.f;
        sA[s][l] = a;
        sC[s][l] = g_X[(size_t)(b * SS + s) * XCOLS + col];
    }
    for (int p = tid; p < SS * SS; p += 128) {
        size_t idx = (size_t)(b * 64 + p / SS) * 64 + p % SS;
        float g = g_Gf[idx];
#pragma unroll
        for (int z = 1; z < GSLABS; z++) g += g_Gf[z * GSTRIDE + idx];
        sG[p / SS][p % SS] = g;
    }
    __syncthreads();

    if (tid < SS) {
        float s2 = 0.f;
#pragma unroll
        for (int l = 0; l < LL; l++) { float v = sA[tid][l]; s2 += v * v; }
        snorm[tid] = 1.f / (sqrtf(s2) + EPSF);
    }
    __syncthreads();

    // Heavy warp (rotates across SMSPs with caption index)
    if ((tid >> 5) == (i & 3)) {
        const int l = tid & 31;
        float vals[SS];
#pragma unroll
        for (int s = 0; s < SS; s++) vals[s] = sA[s][l] * snorm[s] * SMOOTHF;

        float m = vals[0];
#pragma unroll
        for (int s = 1; s < SS; s++) m = fmaxf(m, vals[s]);
        float sum = 0.f;
#pragma unroll
        for (int s = 0; s < SS; s++) { float e = fexp(vals[s] - m); vals[s] = e; sum += e; }
        float inv = 1.f / sum;
#pragma unroll
        for (int s = 0; s < SS; s++) vals[s] *= inv;

        float w12 = 0.f, w2q = 0.f;
#pragma unroll
        for (int s = 0; s < SS; s++) {
            float inner = 0.f;
#pragma unroll
            for (int s2 = 0; s2 < SS; s2++) inner = fmaf(sG[s][s2], vals[s2], inner);
            w2q = fmaf(vals[s], inner, w2q);
            w12 = fmaf(vals[s], sC[s][l], w12);
        }
        float w2 = sqrtf(fmaxf(w2q, 0.f));
        float w1 = g_w1[i * LL + l];
        float r = w12 / fmaxf(w1 * w2, EPSF);

        float z = (l < len) ? r * LAMBDAF : -1e30f;
        float mm = z;
#pragma unroll
        for (int o = 16; o; o >>= 1) mm = fmaxf(mm, __shfl_xor_sync(0xffffffffu, mm, o));
        float e = (l < len) ? fexp(z - mm) : 0.f;
#pragma unroll
        for (int o = 16; o; o >>= 1) e += __shfl_xor_sync(0xffffffffu, e, o);
        if (l == 0) out[b * NB + i] = (logf(e) + mm) / LAMBDAF;
    }
}

// ---------------------------------------------------------------------------
extern "C" void kernel_launch(void* const* d_in, const int* in_sizes, int n_in,
                              void* d_out, int out_size)
{
    const float* images   = (const float*)d_in[0];  // (64, 36, 1024)
    const float* captions = (const float*)d_in[1];  // (64, 32, 1024)
    const int*   cap_lens = (const int*)  d_in[2];  // (64,)
    const float* W_g      = (const float*)d_in[3];  // (1024, 1024)
    float* out = (float*)d_out;                     // (64, 64)

    __half *pA2, *pB2, *pBW;
    float *pX, *pGf;
    cudaGetSymbolAddress((void**)&pA2, g_A2);
    cudaGetSymbolAddress((void**)&pB2, g_B2);
    cudaGetSymbolAddress((void**)&pBW, g_BW);
    cudaGetSymbolAddress((void**)&pX,  g_X);
    cudaGetSymbolAddress((void**)&pGf, g_Gf);

    // P/gram variant: BM=64, BN=64, warps 2x2, 3 stages, 4 CTAs/SM. smem = 50176
    // X variant:      BM=128, BN=128, warps 2x2 (64x64 warp tiles), 3 stages,
    //                 2 CTAs/SM. smem = 3*(128+128)*128 + 1024 = 99328
    const int SMEM_P = 3 * (64 + 64) * 128 + 1024;
    const int SMEM_X = 3 * (128 + 128) * 128 + 1024;
    cudaFuncSetAttribute((const void*)gemm_mma_kernel<64, 64, 2, 2, 3, 4>,
                         cudaFuncAttributeMaxDynamicSharedMemorySize, SMEM_P);
    cudaFuncSetAttribute((const void*)gemm_mma_kernel<128, 128, 2, 2, 3, 2>,
                         cudaFuncAttributeMaxDynamicSharedMemorySize, SMEM_X);

    // 1) fp32 -> fp16 converts + W transpose
    cvt_both_kernel<<<(MROWS + CROWS) * DD / 512, 256>>>(images, captions, pA2, pB2);
    {
        dim3 grid(DD / 32, DD / 32);
        cvt_w_kernel<<<grid, dim3(32, 32)>>>(W_g);
    }

    // 2) GEMM-P: Y = images_h @ W_h -> fp16 into g_A2 rows [2304, 4608)
    {
        dim3 grid(DD / 64, MROWS / 64);
        gemm_mma_kernel<64, 64, 2, 2, 3, 4><<<grid, 128, SMEM_P>>>(
            pA2, pBW, nullptr, pA2 + (size_t)MROWS * KSPLIT, 1, 0, 64, 0, NCHUNK, 0);
    }
    // 3) Gram via tensor cores, split-K: grid (1, 64, 4); each z does 4 chunks (K=256)
    //    writing a partial slab; epilogue sums the 4 slabs.
    {
        dim3 grid(1, NB, GSLABS);
        gemm_mma_kernel<64, 64, 2, 2, 3, 4><<<grid, 128, SMEM_P>>>(
            pA2, pA2, pGf, nullptr, 0, 64, SS, SS, NCHUNK / GSLABS, GSTRIDE);
    }
    // 4) GEMM-X: X = [images_h ; Y_h] @ captions_h^T  (4608 x 2048, fp32)
    //    grid (16, 36) = 576 CTAs, 128 threads, 2 CTAs/SM, 64x64 warp tiles
    {
        dim3 grid(XCOLS / 128, AROWS / 128);
        gemm_mma_kernel<128, 128, 2, 2, 3, 2><<<grid, 128, SMEM_X>>>(
            pA2, pB2, pX, nullptr, 0, XCOLS, 128, 0, NCHUNK, 0);
    }

    // 5) Caption norms (fp32, exact)
    w1_kernel<<<CROWS / 8, 256>>>(captions);

    // 6) Final epilogue
    {
        dim3 grid(NB, NB);
        epilogue_kernel<<<grid, 128>>>(cap_lens, out);
    }
}

// round 15
// speedup vs baseline: 2.5954x; 1.0701x over previous
#include <cuda_runtime.h>
#include <cuda_fp16.h>
#include <math_constants.h>
#include <cstdint>

// Problem constants
#define DD     1024
#define NB     64
#define SS     36
#define LL     32
#define SMOOTHF 9.0f
#define LAMBDAF 6.0f
#define EPSF   1e-8f

#define MROWS  (NB*SS)       // 2304 image rows
#define CROWS  (NB*LL)       // 2048 caption rows
#define AROWS  (2*MROWS)     // 4608 = [images ; Y]
#define KSPLIT 1024          // plain fp16
#define XCOLS  CROWS         // 2048

#define BK 64                        // fp16 elems per chunk = 128 B rows
#define NCHUNK (KSPLIT / BK)         // 16
#define GSLABS 4                     // split-K factor for Gram
#define GSTRIDE ((size_t)NB * 64 * 64)

// Scratch (static device globals; allocation forbidden)
__device__ __half g_A2[(size_t)AROWS * KSPLIT];  // [images_h ; Y_h]
__device__ __half g_B2[(size_t)CROWS * KSPLIT];  // captions_h
__device__ __half g_BW[(size_t)DD   * KSPLIT];   // W_g^T fp16
__device__ float g_X[(size_t)AROWS * XCOLS];     // fused GEMM output fp32
__device__ float g_Gf[GSLABS * NB * 64 * 64];    // split-K partial Grams
__device__ float g_w1[CROWS];

// ---------------------------------------------------------------------------
// PTX helpers (base-ISA only: cp.async, ldmatrix, mma.sync)
// ---------------------------------------------------------------------------
__device__ __forceinline__ uint32_t smem_u32(const void* p) {
    uint32_t a;
    asm("{ .reg .u64 t; cvta.to.shared.u64 t, %1; cvt.u32.u64 %0, t; }" : "=r"(a) : "l"(p));
    return a;
}
#define CP_ASYNC16(dst, src) \
    asm volatile("cp.async.cg.shared.global [%0], [%1], 16;\n" :: "r"(dst), "l"(src))
#define CP_COMMIT() asm volatile("cp.async.commit_group;\n" ::: "memory")
#define CP_WAIT(n)  asm volatile("cp.async.wait_group %0;\n" :: "n"(n) : "memory")

__device__ __forceinline__ void ldsm4(uint32_t* r, uint32_t addr) {
    asm volatile("ldmatrix.sync.aligned.m8n8.x4.shared.b16 {%0,%1,%2,%3}, [%4];"
                 : "=r"(r[0]), "=r"(r[1]), "=r"(r[2]), "=r"(r[3]) : "r"(addr));
}
__device__ __forceinline__ void mma16816(float* c, const uint32_t* a,
                                         uint32_t b0, uint32_t b1) {
    asm volatile("mma.sync.aligned.m16n8k16.row.col.f32.f16.f16.f32 "
                 "{%0,%1,%2,%3}, {%4,%5,%6,%7}, {%8,%9}, {%0,%1,%2,%3};"
                 : "+f"(c[0]), "+f"(c[1]), "+f"(c[2]), "+f"(c[3])
                 : "r"(a[0]), "r"(a[1]), "r"(a[2]), "r"(a[3]), "r"(b0), "r"(b1));
}
// SW128 swizzle for 128B rows
__device__ __forceinline__ uint32_t swz(int row, int seg) {
    return (uint32_t)(row * 128 + (seg ^ ((row & 7) << 4)));
}

// Fast exp on the FMA pipe (no MUFU). Valid for finite x in (-87, 20).
__device__ __forceinline__ float fexp(float x) {
    const float L2E = 1.4426950408889634f;
    float t = fmaf(x, L2E, 12582912.0f);
    float i = t - 12582912.0f;
    float f = fmaf(x, L2E, -i);
    float p = 1.3333558146e-3f;
    p = fmaf(p, f, 9.6181291076e-3f);
    p = fmaf(p, f, 5.5504108665e-2f);
    p = fmaf(p, f, 2.4022650696e-1f);
    p = fmaf(p, f, 6.9314718056e-1f);
    p = fmaf(p, f, 1.0f);
    return __int_as_float(__float_as_int(p) + (((int)i) << 23));
}

// ---------------------------------------------------------------------------
// prep_kernel: fused fp32->fp16 converts (images+captions), W transpose,
// and caption norms, dispatched by flattened block index. 256 threads.
// ---------------------------------------------------------------------------
#define CVT_BLOCKS ((MROWS + CROWS) * DD / 512)   // 8704
#define CVW_BLOCKS (32 * 32)                      // 1024
#define W1_BLOCKS  (CROWS / 8)                    // 256
#define IMG_PAIRS  (MROWS * DD / 2)

__global__ __launch_bounds__(256)
void prep_kernel(const float* __restrict__ images,
                 const float* __restrict__ captions,
                 const float* __restrict__ W,
                 __half* __restrict__ dimg, __half* __restrict__ dcap)
{
    const int blk = blockIdx.x;
    const int tid = threadIdx.x;

    if (blk < CVT_BLOCKS) {
        int i = blk * 256 + tid;
        const float* src; __half* dst; int j;
        if (i < IMG_PAIRS) { src = images;   dst = dimg; j = i; }
        else               { src = captions; dst = dcap; j = i - IMG_PAIRS; }
        float2 v = *(const float2*)(src + 2 * j);
        __half2 h; h.x = __float2half(v.x); h.y = __float2half(v.y);
        *(__half2*)(dst + 2 * j) = h;
    } else if (blk < CVT_BLOCKS + CVW_BLOCKS) {
        __shared__ float t[32][33];
        int wid_ = blk - CVT_BLOCKS;
        int n0 = (wid_ & 31) * 32, k0 = (wid_ >> 5) * 32;
        int tx = tid & 31, ty = tid >> 5;            // 32 x 8
#pragma unroll
        for (int j = 0; j < 4; j++)
            t[ty + 8 * j][tx] = W[(size_t)(k0 + ty + 8 * j) * DD + n0 + tx];
        __syncthreads();
#pragma unroll
        for (int j = 0; j < 4; j++)
            g_BW[(size_t)(n0 + ty + 8 * j) * KSPLIT + k0 + tx] = __float2half(t[tx][ty + 8 * j]);
    } else {
        int r = blk - CVT_BLOCKS - CVW_BLOCKS;
        int row = r * 8 + (tid >> 5);
        int lane = tid & 31;
        const float* p = captions + (size_t)row * DD;
        float s = 0.f;
        for (int k = lane; k < DD; k += 32) { float v = p[k]; s += v * v; }
#pragma unroll
        for (int o = 16; o; o >>= 1) s += __shfl_xor_sync(0xffffffffu, s, o);
        if (lane == 0) g_w1[row] = sqrtf(s);
    }
}

// ---------------------------------------------------------------------------
// Shared GEMM body (BM=64, BN=64, warps 2x2, 3 stages). Used by pg_kernel.
// C[m,n] = sum_{k in window} A[m,k]*B[n,k].
// ---------------------------------------------------------------------------
__device__ __forceinline__ void gemm64_body(
    int bx, int by, int kbase,
    const __half* __restrict__ A, const __half* __restrict__ B,
    float* __restrict__ C, __half* __restrict__ Aout,
    int mode, int ldc, int arowmul, int browadd, int nch,
    char* smem_raw, int tid)
{
    constexpr int STAGES = 3;
    constexpr int MT = 2, NT2 = 2, NJ = 4;
    constexpr int A_BYTES = 64 * 128;
    constexpr int STAGE_BYTES = 2 * A_BYTES;

    const uint32_t sbase = (smem_u32(smem_raw) + 1023u) & ~1023u;
    const int wid = tid >> 5, lane = tid & 31;
    const int wm = wid >> 1;
    const int wn = wid & 1;
    const size_t arow0 = (size_t)by * arowmul;
    const size_t brow0 = (size_t)bx * 64 + (size_t)by * browadd;

    const int lr = lane & 15;
    const int lseg = (lane >> 4) * 16;

    float acc[MT][NJ][4];
#pragma unroll
    for (int mt = 0; mt < MT; mt++)
#pragma unroll
        for (int j = 0; j < NJ; j++)
#pragma unroll
            for (int e = 0; e < 4; e++) acc[mt][j][e] = 0.f;

    uint32_t af[2][MT][4], bf[2][NT2][4];

    const char* Abase = (const char*)(A + arow0 * KSPLIT + (size_t)kbase * BK);
    const char* Bbase = (const char*)(B + brow0 * KSPLIT + (size_t)kbase * BK);
    auto load_chunk = [&](int c, int s) {
        const uint32_t sA = sbase + s * STAGE_BYTES;
        const uint32_t sB = sA + A_BYTES;
        const size_t cb = (size_t)c * 128;
#pragma unroll
        for (int i = 0; i < 4; i++) {
            int p = tid + i * 128;
            int r = p >> 3, seg = (p & 7) * 16;
            CP_ASYNC16(sA + swz(r, seg), Abase + (size_t)r * (KSPLIT * 2) + cb + seg);
        }
#pragma unroll
        for (int i = 0; i < 4; i++) {
            int p = tid + i * 128;
            int r = p >> 3, seg = (p & 7) * 16;
            CP_ASYNC16(sB + swz(r, seg), Bbase + (size_t)r * (KSPLIT * 2) + cb + seg);
        }
        CP_COMMIT();
    };

    auto ldfrag = [&](int s, int kk, int buf) {
        const uint32_t sA = sbase + s * STAGE_BYTES;
        const uint32_t sB = sA + A_BYTES;
#pragma unroll
        for (int mt = 0; mt < MT; mt++)
            ldsm4(af[buf][mt], sA + swz(wm * 32 + mt * 16 + lr, kk * 32 + lseg));
#pragma unroll
        for (int nt = 0; nt < NT2; nt++)
            ldsm4(bf[buf][nt], sB + swz(wn * 32 + nt * 16 + lr, kk * 32 + lseg));
    };

    auto domma = [&](int buf) {
#pragma unroll
        for (int mt = 0; mt < MT; mt++)
#pragma unroll
            for (int nt = 0; nt < NT2; nt++)
#pragma unroll
                for (int h = 0; h < 2; h++)
                    mma16816(acc[mt][nt * 2 + h], af[buf][mt],
                             bf[buf][nt][h], bf[buf][nt][h + 2]);
    };

    load_chunk(0, 0);
    load_chunk(1, 1);

    for (int c = 0; c < nch; c++) {
        if (c + 1 < nch) { CP_WAIT(1); } else { CP_WAIT(0); }
        __syncthreads();
        if (c + 2 < nch) load_chunk(c + 2, (c + 2) % STAGES);
        const int s = c % STAGES;
        ldfrag(s, 0, 0);
#pragma unroll
        for (int kk = 0; kk < 4; kk++) {
            if (kk < 3) ldfrag(s, kk + 1, (kk + 1) & 1);
            domma(kk & 1);
        }
    }

    const size_t crow0 = (size_t)by * 64;
    const int ccol0 = bx * 64;
    const int r0 = lane >> 2;
    const int cb2 = 2 * (lane & 3);
    if (mode == 0) {
#pragma unroll
        for (int mt = 0; mt < MT; mt++) {
#pragma unroll
            for (int j = 0; j < NJ; j++) {
                size_t row = crow0 + wm * 32 + mt * 16 + r0;
                size_t col = ccol0 + wn * 32 + j * 8 + cb2;
                *(float2*)(C + row * ldc + col)       = make_float2(acc[mt][j][0], acc[mt][j][1]);
                *(float2*)(C + (row + 8) * ldc + col) = make_float2(acc[mt][j][2], acc[mt][j][3]);
            }
        }
    } else {
#pragma unroll
        for (int mt = 0; mt < MT; mt++) {
#pragma unroll
            for (int j = 0; j < NJ; j++) {
                int col = ccol0 + wn * 32 + j * 8 + cb2;
#pragma unroll
                for (int h = 0; h < 2; h++) {
                    size_t row = crow0 + wm * 32 + mt * 16 + r0 + h * 8;
                    __half* dr = Aout + row * KSPLIT;
                    __half2 hv;
                    hv.x = __float2half(acc[mt][j][2 * h]);
                    hv.y = __float2half(acc[mt][j][2 * h + 1]);
                    *(__half2*)(dr + col) = hv;
                }
            }
        }
    }
}

// ---------------------------------------------------------------------------
// pg_kernel: fused GEMM-P (576 CTAs) + split-K Gram (256 CTAs).
// ---------------------------------------------------------------------------
#define P_BLOCKS 576

__global__ __launch_bounds__(128, 4)
void pg_kernel(const __half* __restrict__ A2, const __half* __restrict__ BW,
               float* __restrict__ Gf, __half* __restrict__ Yout)
{
    extern __shared__ char smem_raw[];
    const int id = blockIdx.x;
    const int tid = threadIdx.x;

    if (id < P_BLOCKS) {
        // GEMM-P: Y = images_h @ W_h; grid equiv (16, 36)
        int bx = id & 15, by = id >> 4;
        gemm64_body(bx, by, 0, A2, BW, nullptr, Yout,
                    1, 0, 64, 0, NCHUNK, smem_raw, tid);
    } else {
        // Gram: G_b partial = img_h[b] @ img_h[b]^T over K window
        int g = id - P_BLOCKS;
        int by = g & 63, bz = g >> 6;
        gemm64_body(0, by, bz * (NCHUNK / GSLABS), A2, A2,
                    Gf + (size_t)bz * GSTRIDE, nullptr,
                    0, 64, SS, SS, NCHUNK / GSLABS, smem_raw, tid);
    }
}

// ---------------------------------------------------------------------------
// X GEMM: BM=128, BN=256, warps 2x4 (64x64 warp tiles), 4 stages, 1 CTA/SM.
// ---------------------------------------------------------------------------
__global__ __launch_bounds__(256, 1)
void gemm_x_kernel(const __half* __restrict__ A,
                   const __half* __restrict__ B,
                   float* __restrict__ C)
{
    constexpr int STAGES = 4;
    constexpr int MT = 4, NT2 = 4, NJ = 8;
    constexpr int A_BYTES = 128 * 128;
    constexpr int B_BYTES = 256 * 128;
    constexpr int STAGE_BYTES = A_BYTES + B_BYTES;

    extern __shared__ char smem_raw[];
    const uint32_t sbase = (smem_u32(smem_raw) + 1023u) & ~1023u;

    const int tid = threadIdx.x;
    const int wid = tid >> 5, lane = tid & 31;
    const int wm = wid >> 2;          // 0..1
    const int wn = wid & 3;           // 0..3
    const size_t arow0 = (size_t)blockIdx.y * 128;
    const size_t brow0 = (size_t)blockIdx.x * 256;

    const int lr = lane & 15;
    const int lseg = (lane >> 4) * 16;

    float acc[MT][NJ][4];
#pragma unroll
    for (int mt = 0; mt < MT; mt++)
#pragma unroll
        for (int j = 0; j < NJ; j++)
#pragma unroll
            for (int e = 0; e < 4; e++) acc[mt][j][e] = 0.f;

    uint32_t af[2][MT][4], bf[2][NT2][4];

    const char* Abase = (const char*)(A + arow0 * KSPLIT);
    const char* Bbase = (const char*)(B + brow0 * KSPLIT);
    auto load_chunk = [&](int c, int s) {
        const uint32_t sA = sbase + s * STAGE_BYTES;
        const uint32_t sB = sA + A_BYTES;
        const size_t cb = (size_t)c * 128;
#pragma unroll
        for (int i = 0; i < 4; i++) {
            int p = tid + i * 256;
            int r = p >> 3, seg = (p & 7) * 16;
            CP_ASYNC16(sA + swz(r, seg), Abase + (size_t)r * (KSPLIT * 2) + cb + seg);
        }
#pragma unroll
        for (int i = 0; i < 8; i++) {
            int p = tid + i * 256;
            int r = p >> 3, seg = (p & 7) * 16;
            CP_ASYNC16(sB + swz(r, seg), Bbase + (size_t)r * (KSPLIT * 2) + cb + seg);
        }
        CP_COMMIT();
    };

    auto ldfrag = [&](int s, int kk, int buf) {
        const uint32_t sA = sbase + s * STAGE_BYTES;
        const uint32_t sB = sA + A_BYTES;
#pragma unroll
        for (int mt = 0; mt < MT; mt++)
            ldsm4(af[buf][mt], sA + swz(wm * 64 + mt * 16 + lr, kk * 32 + lseg));
#pragma unroll
        for (int nt = 0; nt < NT2; nt++)
            ldsm4(bf[buf][nt], sB + swz(wn * 64 + nt * 16 + lr, kk * 32 + lseg));
    };

    auto domma = [&](int buf) {
#pragma unroll
        for (int mt = 0; mt < MT; mt++)
#pragma unroll
            for (int nt = 0; nt < NT2; nt++)
#pragma unroll
                for (int h = 0; h < 2; h++)
                    mma16816(acc[mt][nt * 2 + h], af[buf][mt],
                             bf[buf][nt][h], bf[buf][nt][h + 2]);
    };

    load_chunk(0, 0);
    load_chunk(1, 1);
    load_chunk(2, 2);

    for (int c = 0; c < NCHUNK; c++) {
        if (c + 2 < NCHUNK)      { CP_WAIT(2); }
        else if (c + 1 < NCHUNK) { CP_WAIT(1); }
        else                     { CP_WAIT(0); }
        __syncthreads();
        if (c + 3 < NCHUNK) load_chunk(c + 3, (c + 3) % STAGES);
        const int s = c % STAGES;
        ldfrag(s, 0, 0);
#pragma unroll
        for (int kk = 0; kk < 4; kk++) {
            if (kk < 3) ldfrag(s, kk + 1, (kk + 1) & 1);
            domma(kk & 1);
        }
    }

    const int r0 = lane >> 2;
    const int cb2 = 2 * (lane & 3);
#pragma unroll
    for (int mt = 0; mt < MT; mt++) {
#pragma unroll
        for (int j = 0; j < NJ; j++) {
            size_t row = arow0 + wm * 64 + mt * 16 + r0;
            size_t col = brow0 + wn * 64 + j * 8 + cb2;
            *(float2*)(C + row * XCOLS + col)       = make_float2(acc[mt][j][0], acc[mt][j][1]);
            *(float2*)(C + (row + 8) * XCOLS + col) = make_float2(acc[mt][j][2], acc[mt][j][3]);
        }
    }
}

// ---------------------------------------------------------------------------
// Final epilogue: one block per (caption i, image b); one heavy warp per block
// (rotated across SMSPs) does softmax + p^T G p with register-resident probs.
// ---------------------------------------------------------------------------
__global__ __launch_bounds__(128)
void epilogue_kernel(const int* __restrict__ cap_lens, float* __restrict__ out)
{
    const int i = blockIdx.x;
    const int b = blockIdx.y;

    __shared__ float sA[SS][LL + 1];
    __shared__ float sC[SS][LL + 1];
    __shared__ float sG[SS][SS];
    __shared__ float snorm[SS];

    const int tid = threadIdx.x;
    const int len = cap_lens[i];

#pragma unroll
    for (int it = 0; it < 9; it++) {
        int p = tid + it * 128;
        int s = p >> 5, l = p & 31;
        size_t col = (size_t)i * LL + l;
        float a = g_X[(size_t)(MROWS + b * SS + s) * XCOLS + col];
        a = (a > 0.f) ? a : 0.1f * a;
        if (l >= len) a = 0.f;
        sA[s][l] = a;
        sC[s][l] = g_X[(size_t)(b * SS + s) * XCOLS + col];
    }
    for (int p = tid; p < SS * SS; p += 128) {
        size_t idx = (size_t)(b * 64 + p / SS) * 64 + p % SS;
        float g = g_Gf[idx];
#pragma unroll
        for (int z = 1; z < GSLABS; z++) g += g_Gf[z * GSTRIDE + idx];
        sG[p / SS][p % SS] = g;
    }
    __syncthreads();

    if (tid < SS) {
        float s2 = 0.f;
#pragma unroll
        for (int l = 0; l < LL; l++) { float v = sA[tid][l]; s2 += v * v; }
        snorm[tid] = 1.f / (sqrtf(s2) + EPSF);
    }
    __syncthreads();

    if ((tid >> 5) == (i & 3)) {
        const int l = tid & 31;
        float vals[SS];
#pragma unroll
        for (int s = 0; s < SS; s++) vals[s] = sA[s][l] * snorm[s] * SMOOTHF;

        float m = vals[0];
#pragma unroll
        for (int s = 1; s < SS; s++) m = fmaxf(m, vals[s]);
        float sum = 0.f;
#pragma unroll
        for (int s = 0; s < SS; s++) { float e = fexp(vals[s] - m); vals[s] = e; sum += e; }
        float inv = 1.f / sum;
#pragma unroll
        for (int s = 0; s < SS; s++) vals[s] *= inv;

        float w12 = 0.f, w2q = 0.f;
#pragma unroll
        for (int s = 0; s < SS; s++) {
            float inner = 0.f;
#pragma unroll
            for (int s2 = 0; s2 < SS; s2++) inner = fmaf(sG[s][s2], vals[s2], inner);
            w2q = fmaf(vals[s], inner, w2q);
            w12 = fmaf(vals[s], sC[s][l], w12);
        }
        float w2 = sqrtf(fmaxf(w2q, 0.f));
        float w1 = g_w1[i * LL + l];
        float r = w12 / fmaxf(w1 * w2, EPSF);

        float z = (l < len) ? r * LAMBDAF : -1e30f;
        float mm = z;
#pragma unroll
        for (int o = 16; o; o >>= 1) mm = fmaxf(mm, __shfl_xor_sync(0xffffffffu, mm, o));
        float e = (l < len) ? fexp(z - mm) : 0.f;
#pragma unroll
        for (int o = 16; o; o >>= 1) e += __shfl_xor_sync(0xffffffffu, e, o);
        if (l == 0) out[b * NB + i] = (logf(e) + mm) / LAMBDAF;
    }
}

// ---------------------------------------------------------------------------
extern "C" void kernel_launch(void* const* d_in, const int* in_sizes, int n_in,
                              void* d_out, int out_size)
{
    const float* images   = (const float*)d_in[0];  // (64, 36, 1024)
    const float* captions = (const float*)d_in[1];  // (64, 32, 1024)
    const int*   cap_lens = (const int*)  d_in[2];  // (64,)
    const float* W_g      = (const float*)d_in[3];  // (1024, 1024)
    float* out = (float*)d_out;                     // (64, 64)

    __half *pA2, *pB2, *pBW;
    float *pX, *pGf;
    cudaGetSymbolAddress((void**)&pA2, g_A2);
    cudaGetSymbolAddress((void**)&pB2, g_B2);
    cudaGetSymbolAddress((void**)&pBW, g_BW);
    cudaGetSymbolAddress((void**)&pX,  g_X);
    cudaGetSymbolAddress((void**)&pGf, g_Gf);

    const int SMEM_PG = 3 * (64 + 64) * 128 + 1024;       // 50176
    const int SMEM_X  = 4 * (128 + 256) * 128 + 1024;     // 197632
    cudaFuncSetAttribute((const void*)pg_kernel,
                         cudaFuncAttributeMaxDynamicSharedMemorySize, SMEM_PG);
    cudaFuncSetAttribute((const void*)gemm_x_kernel,
                         cudaFuncAttributeMaxDynamicSharedMemorySize, SMEM_X);

    // 1) prep: fp16 converts + W transpose + caption norms (one launch)
    prep_kernel<<<CVT_BLOCKS + CVW_BLOCKS + W1_BLOCKS, 256>>>(
        images, captions, W_g, pA2, pB2);

    // 2) P + gram fused (one launch): P -> Y fp16 rows [2304,4608); gram -> 4 slabs
    pg_kernel<<<P_BLOCKS + NB * GSLABS, 128, SMEM_PG>>>(
        pA2, pBW, pGf, pA2 + (size_t)MROWS * KSPLIT);

    // 3) X = [images_h ; Y_h] @ captions_h^T  (4608 x 2048, fp32); grid (8,36)
    {
        dim3 grid(XCOLS / 256, AROWS / 128);
        gemm_x_kernel<<<grid, 256, SMEM_X>>>(pA2, pB2, pX);
    }

    // 4) Final epilogue
    {
        dim3 grid(NB, NB);
        epilogue_kernel<<<grid, 128>>>(cap_lens, out);
    }
}

// round 16
// speedup vs baseline: 3.0460x; 1.1736x over previous
#include <cuda_runtime.h>
#include <cuda_fp16.h>
#include <math_constants.h>
#include <cstdint>

// Problem constants
#define DD     1024
#define NB     64
#define SS     36
#define LL     32
#define SMOOTHF 9.0f
#define LAMBDAF 6.0f
#define EPSF   1e-8f

#define MROWS  (NB*SS)       // 2304 image rows
#define CROWS  (NB*LL)       // 2048 caption rows
#define AROWS  (2*MROWS)     // 4608 = [images ; Y]
#define KSPLIT 1024          // plain fp16
#define XCOLS  CROWS         // 2048

#define BK 64                        // fp16 elems per chunk = 128 B rows
#define NCHUNK (KSPLIT / BK)         // 16
#define GSLABS 4                     // split-K factor for Gram
#define GSTRIDE ((size_t)NB * 64 * 64)

// Scratch (static device globals; allocation forbidden)
__device__ __half g_A2[(size_t)AROWS * KSPLIT];  // [images_h ; Y_h]
__device__ __half g_B2[(size_t)CROWS * KSPLIT];  // captions_h
__device__ __half g_BW[(size_t)DD   * KSPLIT];   // W_g^T fp16
__device__ float g_X[(size_t)AROWS * XCOLS];     // fused GEMM output fp32
__device__ float g_Gf[GSLABS * NB * 64 * 64];    // split-K partial Grams
__device__ float g_w1[CROWS];

// ---------------------------------------------------------------------------
// PTX helpers (base-ISA only: cp.async, ldmatrix, mma.sync)
// ---------------------------------------------------------------------------
__device__ __forceinline__ uint32_t smem_u32(const void* p) {
    uint32_t a;
    asm("{ .reg .u64 t; cvta.to.shared.u64 t, %1; cvt.u32.u64 %0, t; }" : "=r"(a) : "l"(p));
    return a;
}
#define CP_ASYNC16(dst, src) \
    asm volatile("cp.async.cg.shared.global [%0], [%1], 16;\n" :: "r"(dst), "l"(src))
#define CP_COMMIT() asm volatile("cp.async.commit_group;\n" ::: "memory")
#define CP_WAIT(n)  asm volatile("cp.async.wait_group %0;\n" :: "n"(n) : "memory")

__device__ __forceinline__ void ldsm4(uint32_t* r, uint32_t addr) {
    asm volatile("ldmatrix.sync.aligned.m8n8.x4.shared.b16 {%0,%1,%2,%3}, [%4];"
                 : "=r"(r[0]), "=r"(r[1]), "=r"(r[2]), "=r"(r[3]) : "r"(addr));
}
__device__ __forceinline__ void mma16816(float* c, const uint32_t* a,
                                         uint32_t b0, uint32_t b1) {
    asm volatile("mma.sync.aligned.m16n8k16.row.col.f32.f16.f16.f32 "
                 "{%0,%1,%2,%3}, {%4,%5,%6,%7}, {%8,%9}, {%0,%1,%2,%3};"
                 : "+f"(c[0]), "+f"(c[1]), "+f"(c[2]), "+f"(c[3])
                 : "r"(a[0]), "r"(a[1]), "r"(a[2]), "r"(a[3]), "r"(b0), "r"(b1));
}
// SW128 swizzle for 128B rows
__device__ __forceinline__ uint32_t swz(int row, int seg) {
    return (uint32_t)(row * 128 + (seg ^ ((row & 7) << 4)));
}

// Fast exp on the FMA pipe (no MUFU). Valid for finite x in (-87, 20).
__device__ __forceinline__ float fexp(float x) {
    const float L2E = 1.4426950408889634f;
    float t = fmaf(x, L2E, 12582912.0f);
    float i = t - 12582912.0f;
    float f = fmaf(x, L2E, -i);
    float p = 1.3333558146e-3f;
    p = fmaf(p, f, 9.6181291076e-3f);
    p = fmaf(p, f, 5.5504108665e-2f);
    p = fmaf(p, f, 2.4022650696e-1f);
    p = fmaf(p, f, 6.9314718056e-1f);
    p = fmaf(p, f, 1.0f);
    return __int_as_float(__float_as_int(p) + (((int)i) << 23));
}

// ---------------------------------------------------------------------------
// prep_kernel: fused fp32->fp16 converts (images+captions), W transpose,
// and caption norms, dispatched by flattened block index. 256 threads.
// ---------------------------------------------------------------------------
#define CVT_BLOCKS ((MROWS + CROWS) * DD / 512)   // 8704
#define CVW_BLOCKS (32 * 32)                      // 1024
#define W1_BLOCKS  (CROWS / 8)                    // 256
#define IMG_PAIRS  (MROWS * DD / 2)

__global__ __launch_bounds__(256)
void prep_kernel(const float* __restrict__ images,
                 const float* __restrict__ captions,
                 const float* __restrict__ W,
                 __half* __restrict__ dimg, __half* __restrict__ dcap)
{
    const int blk = blockIdx.x;
    const int tid = threadIdx.x;

    if (blk < CVT_BLOCKS) {
        int i = blk * 256 + tid;
        const float* src; __half* dst; int j;
        if (i < IMG_PAIRS) { src = images;   dst = dimg; j = i; }
        else               { src = captions; dst = dcap; j = i - IMG_PAIRS; }
        float2 v = *(const float2*)(src + 2 * j);
        __half2 h; h.x = __float2half(v.x); h.y = __float2half(v.y);
        *(__half2*)(dst + 2 * j) = h;
    } else if (blk < CVT_BLOCKS + CVW_BLOCKS) {
        __shared__ float t[32][33];
        int wid_ = blk - CVT_BLOCKS;
        int n0 = (wid_ & 31) * 32, k0 = (wid_ >> 5) * 32;
        int tx = tid & 31, ty = tid >> 5;            // 32 x 8
#pragma unroll
        for (int j = 0; j < 4; j++)
            t[ty + 8 * j][tx] = W[(size_t)(k0 + ty + 8 * j) * DD + n0 + tx];
        __syncthreads();
#pragma unroll
        for (int j = 0; j < 4; j++)
            g_BW[(size_t)(n0 + ty + 8 * j) * KSPLIT + k0 + tx] = __float2half(t[tx][ty + 8 * j]);
    } else {
        int r = blk - CVT_BLOCKS - CVW_BLOCKS;
        int row = r * 8 + (tid >> 5);
        int lane = tid & 31;
        const float* p = captions + (size_t)row * DD;
        float s = 0.f;
        for (int k = lane; k < DD; k += 32) { float v = p[k]; s += v * v; }
#pragma unroll
        for (int o = 16; o; o >>= 1) s += __shfl_xor_sync(0xffffffffu, s, o);
        if (lane == 0) g_w1[row] = sqrtf(s);
    }
}

// ---------------------------------------------------------------------------
// Shared GEMM body (BM=64, BN=64, warps 2x2, 3 stages). Used by pg_kernel.
// ---------------------------------------------------------------------------
__device__ __forceinline__ void gemm64_body(
    int bx, int by, int kbase,
    const __half* __restrict__ A, const __half* __restrict__ B,
    float* __restrict__ C, __half* __restrict__ Aout,
    int mode, int ldc, int arowmul, int browadd, int nch,
    char* smem_raw, int tid)
{
    constexpr int STAGES = 3;
    constexpr int MT = 2, NT2 = 2, NJ = 4;
    constexpr int A_BYTES = 64 * 128;
    constexpr int STAGE_BYTES = 2 * A_BYTES;

    const uint32_t sbase = (smem_u32(smem_raw) + 1023u) & ~1023u;
    const int wid = tid >> 5, lane = tid & 31;
    const int wm = wid >> 1;
    const int wn = wid & 1;
    const size_t arow0 = (size_t)by * arowmul;
    const size_t brow0 = (size_t)bx * 64 + (size_t)by * browadd;

    const int lr = lane & 15;
    const int lseg = (lane >> 4) * 16;

    float acc[MT][NJ][4];
#pragma unroll
    for (int mt = 0; mt < MT; mt++)
#pragma unroll
        for (int j = 0; j < NJ; j++)
#pragma unroll
            for (int e = 0; e < 4; e++) acc[mt][j][e] = 0.f;

    uint32_t af[2][MT][4], bf[2][NT2][4];

    const char* Abase = (const char*)(A + arow0 * KSPLIT + (size_t)kbase * BK);
    const char* Bbase = (const char*)(B + brow0 * KSPLIT + (size_t)kbase * BK);
    auto load_chunk = [&](int c, int s) {
        const uint32_t sA = sbase + s * STAGE_BYTES;
        const uint32_t sB = sA + A_BYTES;
        const size_t cb = (size_t)c * 128;
#pragma unroll
        for (int i = 0; i < 4; i++) {
            int p = tid + i * 128;
            int r = p >> 3, seg = (p & 7) * 16;
            CP_ASYNC16(sA + swz(r, seg), Abase + (size_t)r * (KSPLIT * 2) + cb + seg);
        }
#pragma unroll
        for (int i = 0; i < 4; i++) {
            int p = tid + i * 128;
            int r = p >> 3, seg = (p & 7) * 16;
            CP_ASYNC16(sB + swz(r, seg), Bbase + (size_t)r * (KSPLIT * 2) + cb + seg);
        }
        CP_COMMIT();
    };

    auto ldfrag = [&](int s, int kk, int buf) {
        const uint32_t sA = sbase + s * STAGE_BYTES;
        const uint32_t sB = sA + A_BYTES;
#pragma unroll
        for (int mt = 0; mt < MT; mt++)
            ldsm4(af[buf][mt], sA + swz(wm * 32 + mt * 16 + lr, kk * 32 + lseg));
#pragma unroll
        for (int nt = 0; nt < NT2; nt++)
            ldsm4(bf[buf][nt], sB + swz(wn * 32 + nt * 16 + lr, kk * 32 + lseg));
    };

    auto domma = [&](int buf) {
#pragma unroll
        for (int mt = 0; mt < MT; mt++)
#pragma unroll
            for (int nt = 0; nt < NT2; nt++)
#pragma unroll
                for (int h = 0; h < 2; h++)
                    mma16816(acc[mt][nt * 2 + h], af[buf][mt],
                             bf[buf][nt][h], bf[buf][nt][h + 2]);
    };

    load_chunk(0, 0);
    load_chunk(1, 1);

    for (int c = 0; c < nch; c++) {
        if (c + 1 < nch) { CP_WAIT(1); } else { CP_WAIT(0); }
        __syncthreads();
        if (c + 2 < nch) load_chunk(c + 2, (c + 2) % STAGES);
        const int s = c % STAGES;
        ldfrag(s, 0, 0);
#pragma unroll
        for (int kk = 0; kk < 4; kk++) {
            if (kk < 3) ldfrag(s, kk + 1, (kk + 1) & 1);
            domma(kk & 1);
        }
    }

    const size_t crow0 = (size_t)by * 64;
    const int ccol0 = bx * 64;
    const int r0 = lane >> 2;
    const int cb2 = 2 * (lane & 3);
    if (mode == 0) {
#pragma unroll
        for (int mt = 0; mt < MT; mt++) {
#pragma unroll
            for (int j = 0; j < NJ; j++) {
                size_t row = crow0 + wm * 32 + mt * 16 + r0;
                size_t col = ccol0 + wn * 32 + j * 8 + cb2;
                *(float2*)(C + row * ldc + col)       = make_float2(acc[mt][j][0], acc[mt][j][1]);
                *(float2*)(C + (row + 8) * ldc + col) = make_float2(acc[mt][j][2], acc[mt][j][3]);
            }
        }
    } else {
#pragma unroll
        for (int mt = 0; mt < MT; mt++) {
#pragma unroll
            for (int j = 0; j < NJ; j++) {
                int col = ccol0 + wn * 32 + j * 8 + cb2;
#pragma unroll
                for (int h = 0; h < 2; h++) {
                    size_t row = crow0 + wm * 32 + mt * 16 + r0 + h * 8;
                    __half* dr = Aout + row * KSPLIT;
                    __half2 hv;
                    hv.x = __float2half(acc[mt][j][2 * h]);
                    hv.y = __float2half(acc[mt][j][2 * h + 1]);
                    *(__half2*)(dr + col) = hv;
                }
            }
        }
    }
}

// ---------------------------------------------------------------------------
// pg_kernel: fused GEMM-P (576 CTAs) + split-K Gram (256 CTAs).
// ---------------------------------------------------------------------------
#define P_BLOCKS 576

__global__ __launch_bounds__(128, 4)
void pg_kernel(const __half* __restrict__ A2, const __half* __restrict__ BW,
               float* __restrict__ Gf, __half* __restrict__ Yout)
{
    extern __shared__ char smem_raw[];
    const int id = blockIdx.x;
    const int tid = threadIdx.x;

    if (id < P_BLOCKS) {
        int bx = id & 15, by = id >> 4;
        gemm64_body(bx, by, 0, A2, BW, nullptr, Yout,
                    1, 0, 64, 0, NCHUNK, smem_raw, tid);
    } else {
        int g = id - P_BLOCKS;
        int by = g & 63, bz = g >> 6;
        gemm64_body(0, by, bz * (NCHUNK / GSLABS), A2, A2,
                    Gf + (size_t)bz * GSTRIDE, nullptr,
                    0, 64, SS, SS, NCHUNK / GSLABS, smem_raw, tid);
    }
}

// ---------------------------------------------------------------------------
// X GEMM: BM=128, BN=256, warps 2x4 (64x64 warp tiles), 4 stages, 1 CTA/SM.
// ---------------------------------------------------------------------------
__global__ __launch_bounds__(256, 1)
void gemm_x_kernel(const __half* __restrict__ A,
                   const __half* __restrict__ B,
                   float* __restrict__ C)
{
    constexpr int STAGES = 4;
    constexpr int MT = 4, NT2 = 4, NJ = 8;
    constexpr int A_BYTES = 128 * 128;
    constexpr int B_BYTES = 256 * 128;
    constexpr int STAGE_BYTES = A_BYTES + B_BYTES;

    extern __shared__ char smem_raw[];
    const uint32_t sbase = (smem_u32(smem_raw) + 1023u) & ~1023u;

    const int tid = threadIdx.x;
    const int wid = tid >> 5, lane = tid & 31;
    const int wm = wid >> 2;
    const int wn = wid & 3;
    const size_t arow0 = (size_t)blockIdx.y * 128;
    const size_t brow0 = (size_t)blockIdx.x * 256;

    const int lr = lane & 15;
    const int lseg = (lane >> 4) * 16;

    float acc[MT][NJ][4];
#pragma unroll
    for (int mt = 0; mt < MT; mt++)
#pragma unroll
        for (int j = 0; j < NJ; j++)
#pragma unroll
            for (int e = 0; e < 4; e++) acc[mt][j][e] = 0.f;

    uint32_t af[2][MT][4], bf[2][NT2][4];

    const char* Abase = (const char*)(A + arow0 * KSPLIT);
    const char* Bbase = (const char*)(B + brow0 * KSPLIT);
    auto load_chunk = [&](int c, int s) {
        const uint32_t sA = sbase + s * STAGE_BYTES;
        const uint32_t sB = sA + A_BYTES;
        const size_t cb = (size_t)c * 128;
#pragma unroll
        for (int i = 0; i < 4; i++) {
            int p = tid + i * 256;
            int r = p >> 3, seg = (p & 7) * 16;
            CP_ASYNC16(sA + swz(r, seg), Abase + (size_t)r * (KSPLIT * 2) + cb + seg);
        }
#pragma unroll
        for (int i = 0; i < 8; i++) {
            int p = tid + i * 256;
            int r = p >> 3, seg = (p & 7) * 16;
            CP_ASYNC16(sB + swz(r, seg), Bbase + (size_t)r * (KSPLIT * 2) + cb + seg);
        }
        CP_COMMIT();
    };

    auto ldfrag = [&](int s, int kk, int buf) {
        const uint32_t sA = sbase + s * STAGE_BYTES;
        const uint32_t sB = sA + A_BYTES;
#pragma unroll
        for (int mt = 0; mt < MT; mt++)
            ldsm4(af[buf][mt], sA + swz(wm * 64 + mt * 16 + lr, kk * 32 + lseg));
#pragma unroll
        for (int nt = 0; nt < NT2; nt++)
            ldsm4(bf[buf][nt], sB + swz(wn * 64 + nt * 16 + lr, kk * 32 + lseg));
    };

    auto domma = [&](int buf) {
#pragma unroll
        for (int mt = 0; mt < MT; mt++)
#pragma unroll
            for (int nt = 0; nt < NT2; nt++)
#pragma unroll
                for (int h = 0; h < 2; h++)
                    mma16816(acc[mt][nt * 2 + h], af[buf][mt],
                             bf[buf][nt][h], bf[buf][nt][h + 2]);
    };

    load_chunk(0, 0);
    load_chunk(1, 1);
    load_chunk(2, 2);

    for (int c = 0; c < NCHUNK; c++) {
        if (c + 2 < NCHUNK)      { CP_WAIT(2); }
        else if (c + 1 < NCHUNK) { CP_WAIT(1); }
        else                     { CP_WAIT(0); }
        __syncthreads();
        if (c + 3 < NCHUNK) load_chunk(c + 3, (c + 3) % STAGES);
        const int s = c % STAGES;
        ldfrag(s, 0, 0);
#pragma unroll
        for (int kk = 0; kk < 4; kk++) {
            if (kk < 3) ldfrag(s, kk + 1, (kk + 1) & 1);
            domma(kk & 1);
        }
    }

    const int r0 = lane >> 2;
    const int cb2 = 2 * (lane & 3);
#pragma unroll
    for (int mt = 0; mt < MT; mt++) {
#pragma unroll
        for (int j = 0; j < NJ; j++) {
            size_t row = arow0 + wm * 64 + mt * 16 + r0;
            size_t col = brow0 + wn * 64 + j * 8 + cb2;
            *(float2*)(C + row * XCOLS + col)       = make_float2(acc[mt][j][0], acc[mt][j][1]);
            *(float2*)(C + (row + 8) * XCOLS + col) = make_float2(acc[mt][j][2], acc[mt][j][3]);
        }
    }
}

// ---------------------------------------------------------------------------
// Final epilogue v2: one block per (image b, 8 captions). 256 threads = 8 warps,
// warp w owns caption i0+w; lane = word. Attention values register-resident;
// Gram staged+slab-summed ONCE per block; symmetric p^T G p (triangular).
// ---------------------------------------------------------------------------
__global__ __launch_bounds__(256)
void epilogue_kernel(const int* __restrict__ cap_lens, float* __restrict__ out)
{
    const int b  = blockIdx.y;
    const int i  = blockIdx.x * 8 + (threadIdx.x >> 5);   // caption
    const int lane = threadIdx.x & 31;                    // word l
    const int tid = threadIdx.x;

    __shared__ float sG[SS][SS];

    // Stage Gram once per block: sum 4 split-K slabs
    for (int p = tid; p < SS * SS; p += 256) {
        size_t idx = (size_t)(b * 64 + p / SS) * 64 + p % SS;
        float g = g_Gf[idx];
#pragma unroll
        for (int z = 1; z < GSLABS; z++) g += g_Gf[z * GSTRIDE + idx];
        sG[p / SS][p % SS] = g;
    }
    __syncthreads();

    const int len = cap_lens[i];
    const size_t colbase = (size_t)i * LL + lane;

    // Load attention logits into registers (lane = word l), leaky + mask
    float a[SS];
#pragma unroll
    for (int s = 0; s < SS; s++) {
        float v = g_X[(size_t)(MROWS + b * SS + s) * XCOLS + colbase];
        v = (v > 0.f) ? v : 0.1f * v;
        if (lane >= len) v = 0.f;
        a[s] = v;
    }

    // Per-region l2 norm over words (butterfly per s), then scale by SMOOTH
#pragma unroll
    for (int s = 0; s < SS; s++) {
        float t = a[s] * a[s];
#pragma unroll
        for (int o = 16; o; o >>= 1) t += __shfl_xor_sync(0xffffffffu, t, o);
        a[s] *= SMOOTHF / (sqrtf(t) + EPSF);
    }

    // Softmax over regions (register-local per lane)
    float m = a[0];
#pragma unroll
    for (int s = 1; s < SS; s++) m = fmaxf(m, a[s]);
    float sum = 0.f;
#pragma unroll
    for (int s = 0; s < SS; s++) { float e = fexp(a[s] - m); a[s] = e; sum += e; }
    float inv = 1.f / sum;
#pragma unroll
    for (int s = 0; s < SS; s++) a[s] *= inv;

    // w12 = p . (cap.img), w2q = p^T G p (symmetric -> triangular)
    float w12 = 0.f, w2q = 0.f;
#pragma unroll
    for (int s = 0; s < SS; s++) {
        float c = g_X[(size_t)(b * SS + s) * XCOLS + colbase];
        w12 = fmaf(a[s], c, w12);
        float inner = 0.f;
#pragma unroll
        for (int s2 = s + 1; s2 < SS; s2++)
            inner = fmaf(sG[s][s2], a[s2], inner);
        w2q = fmaf(2.f * a[s], inner, w2q);
        w2q = fmaf(a[s] * a[s], sG[s][s], w2q);
    }

    float w2 = sqrtf(fmaxf(w2q, 0.f));
    float w1 = g_w1[i * LL + lane];
    float r = w12 / fmaxf(w1 * w2, EPSF);

    // LogSumExp over valid words (lanes)
    float z = (lane < len) ? r * LAMBDAF : -1e30f;
    float mm = z;
#pragma unroll
    for (int o = 16; o; o >>= 1) mm = fmaxf(mm, __shfl_xor_sync(0xffffffffu, mm, o));
    float e = (lane < len) ? fexp(z - mm) : 0.f;
#pragma unroll
    for (int o = 16; o; o >>= 1) e += __shfl_xor_sync(0xffffffffu, e, o);
    if (lane == 0) out[b * NB + i] = (logf(e) + mm) / LAMBDAF;
}

// ---------------------------------------------------------------------------
extern "C" void kernel_launch(void* const* d_in, const int* in_sizes, int n_in,
                              void* d_out, int out_size)
{
    const float* images   = (const float*)d_in[0];  // (64, 36, 1024)
    const float* captions = (const float*)d_in[1];  // (64, 32, 1024)
    const int*   cap_lens = (const int*)  d_in[2];  // (64,)
    const float* W_g      = (const float*)d_in[3];  // (1024, 1024)
    float* out = (float*)d_out;                     // (64, 64)

    __half *pA2, *pB2, *pBW;
    float *pX, *pGf;
    cudaGetSymbolAddress((void**)&pA2, g_A2);
    cudaGetSymbolAddress((void**)&pB2, g_B2);
    cudaGetSymbolAddress((void**)&pBW, g_BW);
    cudaGetSymbolAddress((void**)&pX,  g_X);
    cudaGetSymbolAddress((void**)&pGf, g_Gf);

    const int SMEM_PG = 3 * (64 + 64) * 128 + 1024;       // 50176
    const int SMEM_X  = 4 * (128 + 256) * 128 + 1024;     // 197632
    cudaFuncSetAttribute((const void*)pg_kernel,
                         cudaFuncAttributeMaxDynamicSharedMemorySize, SMEM_PG);
    cudaFuncSetAttribute((const void*)gemm_x_kernel,
                         cudaFuncAttributeMaxDynamicSharedMemorySize, SMEM_X);

    // 1) prep: fp16 converts + W transpose + caption norms (one launch)
    prep_kernel<<<CVT_BLOCKS + CVW_BLOCKS + W1_BLOCKS, 256>>>(
        images, captions, W_g, pA2, pB2);

    // 2) P + gram fused: P -> Y fp16 rows [2304,4608); gram -> 4 partial slabs
    pg_kernel<<<P_BLOCKS + NB * GSLABS, 128, SMEM_PG>>>(
        pA2, pBW, pGf, pA2 + (size_t)MROWS * KSPLIT);

    // 3) X = [images_h ; Y_h] @ captions_h^T  (4608 x 2048, fp32); grid (8,36)
    {
        dim3 grid(XCOLS / 256, AROWS / 128);
        gemm_x_kernel<<<grid, 256, SMEM_X>>>(pA2, pB2, pX);
    }

    // 4) Final epilogue: grid (8, 64), 8 warps = 8 captions per block
    {
        dim3 grid(NB / 8, NB);
        epilogue_kernel<<<grid, 256>>>(cap_lens, out);
    }
}